// round 2
// baseline (speedup 1.0000x reference)
#include <cuda_runtime.h>
#include <math.h>
#include <float.h>

// ---------------------------------------------------------------------------
// MLA forward, fp32 baseline.
//   B=4, T=2048, C=768, H=12, D=64, R=64
// Pipeline:
//   1) q   = x @ Wq                      [8192, 768]
//   2) ckv = x @ Wdown                   [8192, 64]
//   3) layernorm(ckv) over R=64
//   4) kv  = ckv @ Wup                   [8192, 1536]  (k = cols 0..767, v = 768..1535)
//   5) RoPE on q and on k-part of kv
//   6) causal flash attention per (b,h)  -> ao [8192, 768]
//   7) out = ao @ Wo + bo
// ---------------------------------------------------------------------------

#define BB 4
#define TT 2048
#define CC 768
#define HH 12
#define DD 64
#define RR 64
#define MROWS (BB * TT)            // 8192
#define KVW (2 * HH * DD)          // 1536
#define SCALE 0.125f               // D^-0.5

// Scratch (device globals; no allocations allowed)
__device__ float g_q  [MROWS * CC];     // 25 MB
__device__ float g_ckv[MROWS * RR];     //  2 MB
__device__ float g_kv [MROWS * KVW];    // 50 MB
__device__ float g_ao [MROWS * CC];     // 25 MB

// ---------------------------------------------------------------------------
// Generic tiled GEMM: C[M,N] = A[M,K] @ B[K,N] (+ bias)
// 64x64 tile, BK=16, 256 threads, 4x4 micro-tile per thread.
// Requires M%64==0, N%64==0, K%16==0 (true for all our shapes).
// ---------------------------------------------------------------------------
#define GBM 64
#define GBN 64
#define GBK 16

__global__ __launch_bounds__(256) void gemm_kernel(
    const float* __restrict__ A, const float* __restrict__ B,
    const float* __restrict__ bias, float* __restrict__ C,
    int M, int N, int K)
{
    __shared__ float As[GBK][GBM + 4];   // stored transposed: As[k][m]
    __shared__ float Bs[GBK][GBN];

    const int tid = threadIdx.x;
    const int n0 = blockIdx.x * GBN;
    const int m0 = blockIdx.y * GBM;
    const int ty = tid >> 4;             // 0..15
    const int tx = tid & 15;             // 0..15

    const int ar = tid >> 2;             // 0..63 row within A tile
    const int ak = (tid & 3) * 4;        // 0,4,8,12 within k-tile
    const int bk = tid >> 4;             // 0..15
    const int bn = (tid & 15) * 4;       // 0..60

    const float* Aptr = A + (size_t)(m0 + ar) * K + ak;
    const float* Bptr = B + (size_t)bk * N + n0 + bn;

    float acc[4][4];
#pragma unroll
    for (int i = 0; i < 4; ++i)
#pragma unroll
        for (int j = 0; j < 4; ++j) acc[i][j] = 0.f;

    for (int kt = 0; kt < K; kt += GBK) {
        float4 a = *(const float4*)Aptr;
        Aptr += GBK;
        As[ak + 0][ar] = a.x;
        As[ak + 1][ar] = a.y;
        As[ak + 2][ar] = a.z;
        As[ak + 3][ar] = a.w;
        *(float4*)&Bs[bk][bn] = *(const float4*)Bptr;
        Bptr += (size_t)GBK * N;
        __syncthreads();

#pragma unroll
        for (int k = 0; k < GBK; ++k) {
            float4 av = *(const float4*)&As[k][ty * 4];
            float4 bv = *(const float4*)&Bs[k][tx * 4];
            acc[0][0] += av.x * bv.x; acc[0][1] += av.x * bv.y;
            acc[0][2] += av.x * bv.z; acc[0][3] += av.x * bv.w;
            acc[1][0] += av.y * bv.x; acc[1][1] += av.y * bv.y;
            acc[1][2] += av.y * bv.z; acc[1][3] += av.y * bv.w;
            acc[2][0] += av.z * bv.x; acc[2][1] += av.z * bv.y;
            acc[2][2] += av.z * bv.z; acc[2][3] += av.z * bv.w;
            acc[3][0] += av.w * bv.x; acc[3][1] += av.w * bv.y;
            acc[3][2] += av.w * bv.z; acc[3][3] += av.w * bv.w;
        }
        __syncthreads();
    }

    float4 bv4 = make_float4(0.f, 0.f, 0.f, 0.f);
    if (bias) bv4 = *(const float4*)(bias + n0 + tx * 4);
#pragma unroll
    for (int i = 0; i < 4; ++i) {
        float4 o;
        o.x = acc[i][0] + bv4.x;
        o.y = acc[i][1] + bv4.y;
        o.z = acc[i][2] + bv4.z;
        o.w = acc[i][3] + bv4.w;
        *(float4*)(C + (size_t)(m0 + ty * 4 + i) * N + n0 + tx * 4) = o;
    }
}

// ---------------------------------------------------------------------------
// LayerNorm over R=64 per row (warp per row, 8 rows/block)
// ---------------------------------------------------------------------------
__global__ __launch_bounds__(256) void ln_kernel(
    float* __restrict__ ckv, const float* __restrict__ g, const float* __restrict__ bpar)
{
    const int row  = blockIdx.x * 8 + (threadIdx.x >> 5);
    const int lane = threadIdx.x & 31;
    float* ptr = ckv + (size_t)row * RR;
    float v0 = ptr[lane], v1 = ptr[lane + 32];
    float s = v0 + v1, sq = v0 * v0 + v1 * v1;
#pragma unroll
    for (int o = 16; o; o >>= 1) {
        s  += __shfl_xor_sync(0xffffffffu, s,  o);
        sq += __shfl_xor_sync(0xffffffffu, sq, o);
    }
    float mean = s * (1.f / RR);
    float var  = sq * (1.f / RR) - mean * mean;
    float inv  = rsqrtf(var + 1e-5f);
    ptr[lane]      = (v0 - mean) * inv * g[lane]      + bpar[lane];
    ptr[lane + 32] = (v1 - mean) * inv * g[lane + 32] + bpar[lane + 32];
}

// ---------------------------------------------------------------------------
// RoPE (rotate-half). Applies in-place to heads laid out [row, h*64 + d],
// row stride `rowStride` (768 for q, 1536 for kv's K-part).
// ---------------------------------------------------------------------------
__global__ __launch_bounds__(256) void rope_kernel(float* __restrict__ ptr, int rowStride)
{
    int idx = blockIdx.x * blockDim.x + threadIdx.x;   // MROWS*HH*32 total
    if (idx >= MROWS * HH * 32) return;
    int i   = idx & 31;
    int h   = (idx >> 5) % HH;
    int row = idx / (HH * 32);
    int t   = row & (TT - 1);

    float inv = powf(10000.0f, -(float)(2 * i) / (float)DD);
    float ang = (float)t * inv;
    float sn, cs;
    sincosf(ang, &sn, &cs);

    float* base = ptr + (size_t)row * rowStride + h * DD;
    float x0 = base[i], x1 = base[i + 32];
    base[i]      = x0 * cs - x1 * sn;
    base[i + 32] = x1 * cs + x0 * sn;
}

// ---------------------------------------------------------------------------
// Causal flash attention, fp32.
// grid = (T/64, H, B), block = 256.
// Each block handles 64 q rows of one (b,h). 4 lanes per q row:
// lane part p owns score cols [p*16, p*16+16) and output dims [p*16, p*16+16).
// Smem: Qs[64][68], Kt[64][68] (K transposed; reused as P), Vs[64][68].
// ---------------------------------------------------------------------------
#define APAD 68
#define ASMEM_BYTES (3 * 64 * APAD * 4)

__global__ __launch_bounds__(256) void attn_kernel(
    const float* __restrict__ q, const float* __restrict__ kv, float* __restrict__ ao)
{
    extern __shared__ float sm[];
    float* Qs = sm;                 // [64][APAD]
    float* Kt = sm + 64 * APAD;     // [64][APAD]  K^T during S; P during PV
    float* Vs = sm + 2 * 64 * APAD; // [64][APAD]

    const int tid = threadIdx.x;
    const int i0  = blockIdx.x * 64;
    const int h   = blockIdx.y;
    const int b   = blockIdx.z;
    const int r   = tid >> 2;       // q row within tile
    const int p   = tid & 3;        // part

    // --- load Q tile (pre-scaled by D^-0.5) ---
    {
        const int lr = tid >> 2;
        const int ld = (tid & 3) * 16;
        const float* src = q + (size_t)(b * TT + i0 + lr) * CC + h * DD + ld;
        float* dst = Qs + lr * APAD + ld;
#pragma unroll
        for (int j = 0; j < 16; j += 4) {
            float4 v = *(const float4*)(src + j);
            v.x *= SCALE; v.y *= SCALE; v.z *= SCALE; v.w *= SCALE;
            *(float4*)(dst + j) = v;
        }
    }

    float m = -INFINITY, l = 0.f;
    float o[16];
#pragma unroll
    for (int j = 0; j < 16; ++j) o[j] = 0.f;

    const int ntiles = blockIdx.x + 1;
    for (int jt = 0; jt < ntiles; ++jt) {
        const int j0 = jt * 64;
        __syncthreads();   // previous P/V reads done before overwrite

        // --- load K (transposed) and V tiles ---
        {
            const int db = (tid & 15) * 4;
#pragma unroll
            for (int it = 0; it < 4; ++it) {
                const int c = (tid >> 4) + it * 16;
                const size_t rowoff = (size_t)(b * TT + j0 + c) * KVW + h * DD + db;
                float4 kvv = *(const float4*)(kv + rowoff);
                Kt[(db + 0) * APAD + c] = kvv.x;
                Kt[(db + 1) * APAD + c] = kvv.y;
                Kt[(db + 2) * APAD + c] = kvv.z;
                Kt[(db + 3) * APAD + c] = kvv.w;
                float4 vv = *(const float4*)(kv + rowoff + HH * DD);
                *(float4*)(Vs + c * APAD + db) = vv;
            }
        }
        __syncthreads();

        // --- S = Q K^T (16 cols per thread) ---
        float s[16];
#pragma unroll
        for (int cc = 0; cc < 16; ++cc) s[cc] = 0.f;
        const float* qrow = Qs + r * APAD;
        for (int d = 0; d < 64; ++d) {
            float qd = qrow[d];
            const float4* kp = (const float4*)(Kt + d * APAD + p * 16);
            float4 k0 = kp[0], k1 = kp[1], k2 = kp[2], k3 = kp[3];
            s[0]  += qd * k0.x; s[1]  += qd * k0.y; s[2]  += qd * k0.z; s[3]  += qd * k0.w;
            s[4]  += qd * k1.x; s[5]  += qd * k1.y; s[6]  += qd * k1.z; s[7]  += qd * k1.w;
            s[8]  += qd * k2.x; s[9]  += qd * k2.y; s[10] += qd * k2.z; s[11] += qd * k2.w;
            s[12] += qd * k3.x; s[13] += qd * k3.y; s[14] += qd * k3.z; s[15] += qd * k3.w;
        }

        // --- causal mask + online softmax ---
        const int row_g = i0 + r;
        float tmax = -INFINITY;
#pragma unroll
        for (int cc = 0; cc < 16; ++cc) {
            int col = j0 + p * 16 + cc;
            if (col > row_g) s[cc] = -INFINITY;
            tmax = fmaxf(tmax, s[cc]);
        }
        tmax = fmaxf(tmax, __shfl_xor_sync(0xffffffffu, tmax, 1));
        tmax = fmaxf(tmax, __shfl_xor_sync(0xffffffffu, tmax, 2));
        float m_new = fmaxf(m, tmax);
        float alpha = __expf(m - m_new);
        float lsum = 0.f;
#pragma unroll
        for (int cc = 0; cc < 16; ++cc) {
            s[cc] = __expf(s[cc] - m_new);
            lsum += s[cc];
        }
        lsum += __shfl_xor_sync(0xffffffffu, lsum, 1);
        lsum += __shfl_xor_sync(0xffffffffu, lsum, 2);
        l = l * alpha + lsum;
        m = m_new;
#pragma unroll
        for (int j = 0; j < 16; ++j) o[j] *= alpha;

        __syncthreads();   // all S reads of Kt complete
        // --- store P into Kt buffer ---
        {
            float* prow = Kt + r * APAD + p * 16;
#pragma unroll
            for (int cc = 0; cc < 16; cc += 4)
                *(float4*)(prow + cc) = make_float4(s[cc], s[cc + 1], s[cc + 2], s[cc + 3]);
        }
        __syncthreads();

        // --- O += P V ---
        const float* prow = Kt + r * APAD;
        for (int c = 0; c < 64; c += 4) {
            float4 pq = *(const float4*)(prow + c);
            const float4* v0 = (const float4*)(Vs + (c + 0) * APAD + p * 16);
            const float4* v1 = (const float4*)(Vs + (c + 1) * APAD + p * 16);
            const float4* v2 = (const float4*)(Vs + (c + 2) * APAD + p * 16);
            const float4* v3 = (const float4*)(Vs + (c + 3) * APAD + p * 16);
#pragma unroll
            for (int j = 0; j < 4; ++j) {
                float4 a = v0[j];
                o[4 * j + 0] += pq.x * a.x; o[4 * j + 1] += pq.x * a.y;
                o[4 * j + 2] += pq.x * a.z; o[4 * j + 3] += pq.x * a.w;
                float4 bb2 = v1[j];
                o[4 * j + 0] += pq.y * bb2.x; o[4 * j + 1] += pq.y * bb2.y;
                o[4 * j + 2] += pq.y * bb2.z; o[4 * j + 3] += pq.y * bb2.w;
                float4 cc2 = v2[j];
                o[4 * j + 0] += pq.z * cc2.x; o[4 * j + 1] += pq.z * cc2.y;
                o[4 * j + 2] += pq.z * cc2.z; o[4 * j + 3] += pq.z * cc2.w;
                float4 dd2 = v3[j];
                o[4 * j + 0] += pq.w * dd2.x; o[4 * j + 1] += pq.w * dd2.y;
                o[4 * j + 2] += pq.w * dd2.z; o[4 * j + 3] += pq.w * dd2.w;
            }
        }
    }

    // --- finalize ---
    float inv = 1.f / l;
    float* dst = ao + (size_t)(b * TT + i0 + r) * CC + h * DD + p * 16;
#pragma unroll
    for (int j = 0; j < 16; j += 4) {
        float4 v = make_float4(o[j] * inv, o[j + 1] * inv, o[j + 2] * inv, o[j + 3] * inv);
        *(float4*)(dst + j) = v;
    }
}

// ---------------------------------------------------------------------------
// Launch
// ---------------------------------------------------------------------------
extern "C" void kernel_launch(void* const* d_in, const int* in_sizes, int n_in,
                              void* d_out, int out_size)
{
    const float* x     = (const float*)d_in[0];
    const float* Wq    = (const float*)d_in[1];
    const float* Wdown = (const float*)d_in[2];
    const float* ln_g  = (const float*)d_in[3];
    const float* ln_b  = (const float*)d_in[4];
    const float* Wup   = (const float*)d_in[5];
    const float* Wo    = (const float*)d_in[6];
    const float* bo    = (const float*)d_in[7];
    float* out = (float*)d_out;

    void *pq, *pckv, *pkv, *pao;
    cudaGetSymbolAddress(&pq,   g_q);
    cudaGetSymbolAddress(&pckv, g_ckv);
    cudaGetSymbolAddress(&pkv,  g_kv);
    cudaGetSymbolAddress(&pao,  g_ao);
    float* q   = (float*)pq;
    float* ckv = (float*)pckv;
    float* kv  = (float*)pkv;
    float* ao  = (float*)pao;

    cudaFuncSetAttribute(attn_kernel, cudaFuncAttributeMaxDynamicSharedMemorySize, ASMEM_BYTES);

    // 1) q = x @ Wq
    gemm_kernel<<<dim3(CC / GBN, MROWS / GBM), 256>>>(x, Wq, nullptr, q, MROWS, CC, CC);
    // 2) ckv = x @ Wdown
    gemm_kernel<<<dim3(RR / GBN, MROWS / GBM), 256>>>(x, Wdown, nullptr, ckv, MROWS, RR, CC);
    // 3) layernorm
    ln_kernel<<<MROWS / 8, 256>>>(ckv, ln_g, ln_b);
    // 4) kv = ckv @ Wup
    gemm_kernel<<<dim3(KVW / GBN, MROWS / GBM), 256>>>(ckv, Wup, nullptr, kv, MROWS, KVW, RR);
    // 5) RoPE on q and on k-part of kv
    {
        int total = MROWS * HH * 32;
        int blocks = (total + 255) / 256;
        rope_kernel<<<blocks, 256>>>(q, CC);
        rope_kernel<<<blocks, 256>>>(kv, KVW);
    }
    // 6) attention
    attn_kernel<<<dim3(TT / 64, HH, BB), 256, ASMEM_BYTES>>>(q, kv, ao);
    // 7) out = ao @ Wo + bo
    gemm_kernel<<<dim3(CC / GBN, MROWS / GBM), 256>>>(ao, Wo, bo, out, MROWS, CC, CC);
}

// round 3
// speedup vs baseline: 5.1123x; 5.1123x over previous
#include <cuda_runtime.h>
#include <math.h>
#include <float.h>

// ---------------------------------------------------------------------------
// MLA forward, tf32 tensor-core version.
//   B=4, T=2048, C=768, H=12, D=64, R=64
// ---------------------------------------------------------------------------

#define BB 4
#define TT 2048
#define CC 768
#define HH 12
#define DD 64
#define RR 64
#define MROWS (BB * TT)            // 8192
#define KVW (2 * HH * DD)          // 1536
#define SCALE 0.125f               // D^-0.5

// Scratch (device globals; no allocations allowed)
__device__ float g_q  [MROWS * CC];
__device__ float g_ckv[MROWS * RR];
__device__ float g_kv [MROWS * KVW];
__device__ float g_ao [MROWS * CC];

// ---------------------------------------------------------------------------
// tf32 helpers
// ---------------------------------------------------------------------------
__device__ __forceinline__ unsigned f2t(float f) {
    unsigned r;
    asm("cvt.rna.tf32.f32 %0, %1;" : "=r"(r) : "f"(f));
    return r;
}

// D += A(16x8) * B(8x8), tf32 in, fp32 acc. A row-major, B col-major.
__device__ __forceinline__ void mma8(float* c, const unsigned* a, const unsigned* b) {
    asm volatile(
        "mma.sync.aligned.m16n8k8.row.col.f32.tf32.tf32.f32 "
        "{%0,%1,%2,%3},{%4,%5,%6,%7},{%8,%9},{%0,%1,%2,%3};"
        : "+f"(c[0]), "+f"(c[1]), "+f"(c[2]), "+f"(c[3])
        : "r"(a[0]), "r"(a[1]), "r"(a[2]), "r"(a[3]), "r"(b[0]), "r"(b[1]));
}

// ---------------------------------------------------------------------------
// tf32 MMA GEMM: C[M,N] = A[M,K] @ B[K,N] (+ bias)
// 128x128 block tile, BK=16, 256 threads (8 warps, 4m x 2n), warp tile 32x64.
// Requires M%128==0, N%128==0, K%16==0.
// ---------------------------------------------------------------------------
__global__ __launch_bounds__(256) void mma_gemm(
    const float* __restrict__ A, const float* __restrict__ B,
    const float* __restrict__ bias, float* __restrict__ C,
    int M, int N, int K)
{
    __shared__ unsigned As[128][20];   // [m][k], tf32 bits
    __shared__ unsigned Bs[128][20];   // [n][k], tf32 bits (B transposed)

    const int tid  = threadIdx.x;
    const int lane = tid & 31;
    const int w    = tid >> 5;
    const int g    = lane >> 2;
    const int tig  = lane & 3;
    const int wm   = (w & 3) * 32;     // warp m offset
    const int wn   = (w >> 2) * 64;    // warp n offset
    const int m0   = blockIdx.y * 128;
    const int n0   = blockIdx.x * 128;

    // global load mapping
    const int ar   = tid >> 1;         // 0..127 (A row)
    const int ac   = (tid & 1) * 8;    // 0 or 8 (A k offset)
    const int bk   = tid >> 4;         // 0..15  (B k row)
    const int bn16 = tid & 15;         // B n base (stride 16)

    float4 pa0, pa1;
    float  pb[8];

    const float* Abase = A + (size_t)(m0 + ar) * K + ac;
    const float* Bbase = B + (size_t)bk * N + n0 + bn16;

    float acc[2][8][4];
#pragma unroll
    for (int mt = 0; mt < 2; ++mt)
#pragma unroll
        for (int nt = 0; nt < 8; ++nt)
#pragma unroll
            for (int i = 0; i < 4; ++i) acc[mt][nt][i] = 0.f;

    // prologue: load tile 0
    {
        const float* ap = Abase;
        pa0 = *(const float4*)ap; pa1 = *(const float4*)(ap + 4);
        const float* bp = Bbase;
#pragma unroll
        for (int j = 0; j < 8; ++j) pb[j] = bp[j * 16];
    }
    {
        uint4 v0 = make_uint4(f2t(pa0.x), f2t(pa0.y), f2t(pa0.z), f2t(pa0.w));
        uint4 v1 = make_uint4(f2t(pa1.x), f2t(pa1.y), f2t(pa1.z), f2t(pa1.w));
        *(uint4*)&As[ar][ac]     = v0;
        *(uint4*)&As[ar][ac + 4] = v1;
#pragma unroll
        for (int j = 0; j < 8; ++j) Bs[bn16 + j * 16][bk] = f2t(pb[j]);
    }
    __syncthreads();

    for (int kt = 16; ; kt += 16) {
        const bool more = (kt < K);
        if (more) {
            const float* ap = Abase + kt;
            pa0 = *(const float4*)ap; pa1 = *(const float4*)(ap + 4);
            const float* bp = Bbase + (size_t)kt * N;
#pragma unroll
            for (int j = 0; j < 8; ++j) pb[j] = bp[j * 16];
        }

#pragma unroll
        for (int kc = 0; kc < 2; ++kc) {
            const int kb = kc * 8;
            unsigned a[2][4], bf[8][2];
#pragma unroll
            for (int mt = 0; mt < 2; ++mt) {
                const int rb = wm + mt * 16;
                a[mt][0] = As[rb + g][kb + tig];
                a[mt][1] = As[rb + g + 8][kb + tig];
                a[mt][2] = As[rb + g][kb + tig + 4];
                a[mt][3] = As[rb + g + 8][kb + tig + 4];
            }
#pragma unroll
            for (int nt = 0; nt < 8; ++nt) {
                const int nb = wn + nt * 8;
                bf[nt][0] = Bs[nb + g][kb + tig];
                bf[nt][1] = Bs[nb + g][kb + tig + 4];
            }
#pragma unroll
            for (int mt = 0; mt < 2; ++mt)
#pragma unroll
                for (int nt = 0; nt < 8; ++nt)
                    mma8(acc[mt][nt], a[mt], bf[nt]);
        }

        if (!more) break;
        __syncthreads();
        {
            uint4 v0 = make_uint4(f2t(pa0.x), f2t(pa0.y), f2t(pa0.z), f2t(pa0.w));
            uint4 v1 = make_uint4(f2t(pa1.x), f2t(pa1.y), f2t(pa1.z), f2t(pa1.w));
            *(uint4*)&As[ar][ac]     = v0;
            *(uint4*)&As[ar][ac + 4] = v1;
#pragma unroll
            for (int j = 0; j < 8; ++j) Bs[bn16 + j * 16][bk] = f2t(pb[j]);
        }
        __syncthreads();
    }

    // epilogue
#pragma unroll
    for (int mt = 0; mt < 2; ++mt) {
        const int r0 = m0 + wm + mt * 16 + g;
#pragma unroll
        for (int nt = 0; nt < 8; ++nt) {
            const int c0 = n0 + wn + nt * 8 + 2 * tig;
            float b0 = 0.f, b1 = 0.f;
            if (bias) { b0 = bias[c0]; b1 = bias[c0 + 1]; }
            *(float2*)(C + (size_t)r0 * N + c0) =
                make_float2(acc[mt][nt][0] + b0, acc[mt][nt][1] + b1);
            *(float2*)(C + (size_t)(r0 + 8) * N + c0) =
                make_float2(acc[mt][nt][2] + b0, acc[mt][nt][3] + b1);
        }
    }
}

// ---------------------------------------------------------------------------
// Scalar GEMM (kept for Wdown: N=64). 64x64 tile, BK=16.
// ---------------------------------------------------------------------------
#define GBM 64
#define GBN 64
#define GBK 16

__global__ __launch_bounds__(256) void gemm_kernel(
    const float* __restrict__ A, const float* __restrict__ B,
    const float* __restrict__ bias, float* __restrict__ C,
    int M, int N, int K)
{
    __shared__ float As[GBK][GBM + 4];
    __shared__ float Bs[GBK][GBN];

    const int tid = threadIdx.x;
    const int n0 = blockIdx.x * GBN;
    const int m0 = blockIdx.y * GBM;
    const int ty = tid >> 4, tx = tid & 15;
    const int ar = tid >> 2, ak = (tid & 3) * 4;
    const int bk = tid >> 4, bn = (tid & 15) * 4;

    const float* Aptr = A + (size_t)(m0 + ar) * K + ak;
    const float* Bptr = B + (size_t)bk * N + n0 + bn;

    float acc[4][4];
#pragma unroll
    for (int i = 0; i < 4; ++i)
#pragma unroll
        for (int j = 0; j < 4; ++j) acc[i][j] = 0.f;

    for (int kt = 0; kt < K; kt += GBK) {
        float4 a = *(const float4*)Aptr;
        Aptr += GBK;
        As[ak + 0][ar] = a.x; As[ak + 1][ar] = a.y;
        As[ak + 2][ar] = a.z; As[ak + 3][ar] = a.w;
        *(float4*)&Bs[bk][bn] = *(const float4*)Bptr;
        Bptr += (size_t)GBK * N;
        __syncthreads();
#pragma unroll
        for (int k = 0; k < GBK; ++k) {
            float4 av = *(const float4*)&As[k][ty * 4];
            float4 bv = *(const float4*)&Bs[k][tx * 4];
            acc[0][0] += av.x * bv.x; acc[0][1] += av.x * bv.y;
            acc[0][2] += av.x * bv.z; acc[0][3] += av.x * bv.w;
            acc[1][0] += av.y * bv.x; acc[1][1] += av.y * bv.y;
            acc[1][2] += av.y * bv.z; acc[1][3] += av.y * bv.w;
            acc[2][0] += av.z * bv.x; acc[2][1] += av.z * bv.y;
            acc[2][2] += av.z * bv.z; acc[2][3] += av.z * bv.w;
            acc[3][0] += av.w * bv.x; acc[3][1] += av.w * bv.y;
            acc[3][2] += av.w * bv.z; acc[3][3] += av.w * bv.w;
        }
        __syncthreads();
    }

    float4 bv4 = make_float4(0.f, 0.f, 0.f, 0.f);
    if (bias) bv4 = *(const float4*)(bias + n0 + tx * 4);
#pragma unroll
    for (int i = 0; i < 4; ++i) {
        float4 o;
        o.x = acc[i][0] + bv4.x; o.y = acc[i][1] + bv4.y;
        o.z = acc[i][2] + bv4.z; o.w = acc[i][3] + bv4.w;
        *(float4*)(C + (size_t)(m0 + ty * 4 + i) * N + n0 + tx * 4) = o;
    }
}

// ---------------------------------------------------------------------------
// LayerNorm over R=64 per row
// ---------------------------------------------------------------------------
__global__ __launch_bounds__(256) void ln_kernel(
    float* __restrict__ ckv, const float* __restrict__ g, const float* __restrict__ bpar)
{
    const int row  = blockIdx.x * 8 + (threadIdx.x >> 5);
    const int lane = threadIdx.x & 31;
    float* ptr = ckv + (size_t)row * RR;
    float v0 = ptr[lane], v1 = ptr[lane + 32];
    float s = v0 + v1, sq = v0 * v0 + v1 * v1;
#pragma unroll
    for (int o = 16; o; o >>= 1) {
        s  += __shfl_xor_sync(0xffffffffu, s,  o);
        sq += __shfl_xor_sync(0xffffffffu, sq, o);
    }
    float mean = s * (1.f / RR);
    float var  = sq * (1.f / RR) - mean * mean;
    float inv  = rsqrtf(var + 1e-5f);
    ptr[lane]      = (v0 - mean) * inv * g[lane]      + bpar[lane];
    ptr[lane + 32] = (v1 - mean) * inv * g[lane + 32] + bpar[lane + 32];
}

// ---------------------------------------------------------------------------
// RoPE (rotate-half), in-place
// ---------------------------------------------------------------------------
__global__ __launch_bounds__(256) void rope_kernel(float* __restrict__ ptr, int rowStride)
{
    int idx = blockIdx.x * blockDim.x + threadIdx.x;
    if (idx >= MROWS * HH * 32) return;
    int i   = idx & 31;
    int h   = (idx >> 5) % HH;
    int row = idx / (HH * 32);
    int t   = row & (TT - 1);

    float inv = powf(10000.0f, -(float)(2 * i) / (float)DD);
    float ang = (float)t * inv;
    float sn, cs;
    sincosf(ang, &sn, &cs);

    float* base = ptr + (size_t)row * rowStride + h * DD;
    float x0 = base[i], x1 = base[i + 32];
    base[i]      = x0 * cs - x1 * sn;
    base[i + 32] = x1 * cs + x0 * sn;
}

// ---------------------------------------------------------------------------
// Causal flash attention, tf32 MMA.
// grid = (T/64, H, B), block = 128 (4 warps). Warp w owns q rows [w*16,w*16+16).
// Smem (tf32 bits): QP[64][68] (Q tile, then reused as P), Ks[64][68], Vt[64][68].
// ---------------------------------------------------------------------------
#define AP 68
#define ASMEM_BYTES (3 * 64 * AP * 4)

__global__ __launch_bounds__(128) void attn_mma(
    const float* __restrict__ q, const float* __restrict__ kv, float* __restrict__ ao)
{
    extern __shared__ unsigned smu[];
    unsigned* QP = smu;               // [64][AP]
    unsigned* Ks = smu + 64 * AP;     // [64][AP]  K rows (seq major)
    unsigned* Vt = smu + 2 * 64 * AP; // [64][AP]  V transposed (d major)

    const int tid  = threadIdx.x;
    const int lane = tid & 31;
    const int w    = tid >> 5;
    const int g    = lane >> 2;
    const int tig  = lane & 3;
    const int i0   = blockIdx.x * 64;
    const int h    = blockIdx.y;
    const int b    = blockIdx.z;
    const int rb   = w * 16;

    // load Q tile (scaled, tf32) — each warp loads its own 16 rows
    {
        const int r2 = tid >> 1, hh = (tid & 1) * 32;
        const float* src = q + (size_t)(b * TT + i0 + r2) * CC + h * DD + hh;
        unsigned* dst = QP + r2 * AP + hh;
#pragma unroll
        for (int j = 0; j < 32; j += 4) {
            float4 v = *(const float4*)(src + j);
            dst[j + 0] = f2t(v.x * SCALE); dst[j + 1] = f2t(v.y * SCALE);
            dst[j + 2] = f2t(v.z * SCALE); dst[j + 3] = f2t(v.w * SCALE);
        }
    }
    __syncwarp();

    // Q fragments (row-major A): 8 k-chunks over D=64
    unsigned qa[8][4];
#pragma unroll
    for (int kk = 0; kk < 8; ++kk) {
        const int kb = kk * 8;
        qa[kk][0] = QP[(rb + g) * AP + kb + tig];
        qa[kk][1] = QP[(rb + g + 8) * AP + kb + tig];
        qa[kk][2] = QP[(rb + g) * AP + kb + tig + 4];
        qa[kk][3] = QP[(rb + g + 8) * AP + kb + tig + 4];
    }

    float mr0 = -INFINITY, mr1 = -INFINITY, l0 = 0.f, l1 = 0.f;
    float oacc[8][4];
#pragma unroll
    for (int nt = 0; nt < 8; ++nt)
#pragma unroll
        for (int i = 0; i < 4; ++i) oacc[nt][i] = 0.f;

    const int ntile = blockIdx.x + 1;
    for (int jt = 0; jt < ntile; ++jt) {
        const int j0 = jt * 64;
        __syncthreads();   // prev S/PV reads of Ks/Vt complete

        // load K straight, V transposed (tf32)
        {
            const int r2 = tid >> 1, hh = (tid & 1) * 32;
            const float* kp = kv + (size_t)(b * TT + j0 + r2) * KVW + h * DD + hh;
#pragma unroll
            for (int j = 0; j < 32; j += 4) {
                float4 kvv = *(const float4*)(kp + j);
                unsigned* kd = Ks + r2 * AP + hh + j;
                kd[0] = f2t(kvv.x); kd[1] = f2t(kvv.y);
                kd[2] = f2t(kvv.z); kd[3] = f2t(kvv.w);
                float4 vv = *(const float4*)(kp + j + HH * DD);
                Vt[(hh + j + 0) * AP + r2] = f2t(vv.x);
                Vt[(hh + j + 1) * AP + r2] = f2t(vv.y);
                Vt[(hh + j + 2) * AP + r2] = f2t(vv.z);
                Vt[(hh + j + 3) * AP + r2] = f2t(vv.w);
            }
        }
        __syncthreads();

        // S = Q K^T  (warp computes 16 x 64)
        float sacc[8][4];
#pragma unroll
        for (int nt = 0; nt < 8; ++nt)
#pragma unroll
            for (int i = 0; i < 4; ++i) sacc[nt][i] = 0.f;
#pragma unroll
        for (int kk = 0; kk < 8; ++kk) {
            const int kb = kk * 8;
#pragma unroll
            for (int nt = 0; nt < 8; ++nt) {
                unsigned bf[2];
                bf[0] = Ks[(nt * 8 + g) * AP + kb + tig];
                bf[1] = Ks[(nt * 8 + g) * AP + kb + tig + 4];
                mma8(sacc[nt], qa[kk], bf);
            }
        }

        // causal mask (only the diagonal tile needs it)
        if (jt == ntile - 1) {
            const int r0g = i0 + rb + g, r1g = r0g + 8;
#pragma unroll
            for (int nt = 0; nt < 8; ++nt) {
                const int c = j0 + nt * 8 + 2 * tig;
                if (c > r0g)     sacc[nt][0] = -INFINITY;
                if (c + 1 > r0g) sacc[nt][1] = -INFINITY;
                if (c > r1g)     sacc[nt][2] = -INFINITY;
                if (c + 1 > r1g) sacc[nt][3] = -INFINITY;
            }
        }

        // online softmax (rows g and g+8 of this warp's tile)
        float tm0 = -INFINITY, tm1 = -INFINITY;
#pragma unroll
        for (int nt = 0; nt < 8; ++nt) {
            tm0 = fmaxf(tm0, fmaxf(sacc[nt][0], sacc[nt][1]));
            tm1 = fmaxf(tm1, fmaxf(sacc[nt][2], sacc[nt][3]));
        }
        tm0 = fmaxf(tm0, __shfl_xor_sync(0xffffffffu, tm0, 1));
        tm0 = fmaxf(tm0, __shfl_xor_sync(0xffffffffu, tm0, 2));
        tm1 = fmaxf(tm1, __shfl_xor_sync(0xffffffffu, tm1, 1));
        tm1 = fmaxf(tm1, __shfl_xor_sync(0xffffffffu, tm1, 2));

        const float mn0 = fmaxf(mr0, tm0), mn1 = fmaxf(mr1, tm1);
        const float al0 = __expf(mr0 - mn0), al1 = __expf(mr1 - mn1);
        float s0 = 0.f, s1 = 0.f;
#pragma unroll
        for (int nt = 0; nt < 8; ++nt) {
            sacc[nt][0] = __expf(sacc[nt][0] - mn0);
            sacc[nt][1] = __expf(sacc[nt][1] - mn0);
            sacc[nt][2] = __expf(sacc[nt][2] - mn1);
            sacc[nt][3] = __expf(sacc[nt][3] - mn1);
            s0 += sacc[nt][0] + sacc[nt][1];
            s1 += sacc[nt][2] + sacc[nt][3];
        }
        s0 += __shfl_xor_sync(0xffffffffu, s0, 1);
        s0 += __shfl_xor_sync(0xffffffffu, s0, 2);
        s1 += __shfl_xor_sync(0xffffffffu, s1, 1);
        s1 += __shfl_xor_sync(0xffffffffu, s1, 2);
        l0 = l0 * al0 + s0;
        l1 = l1 * al1 + s1;
        mr0 = mn0; mr1 = mn1;
#pragma unroll
        for (int nt = 0; nt < 8; ++nt) {
            oacc[nt][0] *= al0; oacc[nt][1] *= al0;
            oacc[nt][2] *= al1; oacc[nt][3] *= al1;
        }

        // store P into QP (warp-private rows; Q fragments already in regs)
#pragma unroll
        for (int nt = 0; nt < 8; ++nt) {
            const int c = nt * 8 + 2 * tig;
            QP[(rb + g) * AP + c]         = f2t(sacc[nt][0]);
            QP[(rb + g) * AP + c + 1]     = f2t(sacc[nt][1]);
            QP[(rb + g + 8) * AP + c]     = f2t(sacc[nt][2]);
            QP[(rb + g + 8) * AP + c + 1] = f2t(sacc[nt][3]);
        }
        __syncwarp();

        // O += P V   (A = P rows, B = Vt[d][seq] col-major)
#pragma unroll
        for (int kk = 0; kk < 8; ++kk) {
            const int kb = kk * 8;
            unsigned pa[4];
            pa[0] = QP[(rb + g) * AP + kb + tig];
            pa[1] = QP[(rb + g + 8) * AP + kb + tig];
            pa[2] = QP[(rb + g) * AP + kb + tig + 4];
            pa[3] = QP[(rb + g + 8) * AP + kb + tig + 4];
#pragma unroll
            for (int nt = 0; nt < 8; ++nt) {
                unsigned bf[2];
                bf[0] = Vt[(nt * 8 + g) * AP + kb + tig];
                bf[1] = Vt[(nt * 8 + g) * AP + kb + tig + 4];
                mma8(oacc[nt], pa, bf);
            }
        }
    }

    // finalize
    const float inv0 = 1.f / l0, inv1 = 1.f / l1;
    float* dst0 = ao + (size_t)(b * TT + i0 + rb + g) * CC + h * DD;
    float* dst1 = dst0 + (size_t)8 * CC;
#pragma unroll
    for (int nt = 0; nt < 8; ++nt) {
        const int c = nt * 8 + 2 * tig;
        *(float2*)(dst0 + c) = make_float2(oacc[nt][0] * inv0, oacc[nt][1] * inv0);
        *(float2*)(dst1 + c) = make_float2(oacc[nt][2] * inv1, oacc[nt][3] * inv1);
    }
}

// ---------------------------------------------------------------------------
// Launch
// ---------------------------------------------------------------------------
extern "C" void kernel_launch(void* const* d_in, const int* in_sizes, int n_in,
                              void* d_out, int out_size)
{
    const float* x     = (const float*)d_in[0];
    const float* Wq    = (const float*)d_in[1];
    const float* Wdown = (const float*)d_in[2];
    const float* ln_g  = (const float*)d_in[3];
    const float* ln_b  = (const float*)d_in[4];
    const float* Wup   = (const float*)d_in[5];
    const float* Wo    = (const float*)d_in[6];
    const float* bo    = (const float*)d_in[7];
    float* out = (float*)d_out;

    void *pq, *pckv, *pkv, *pao;
    cudaGetSymbolAddress(&pq,   g_q);
    cudaGetSymbolAddress(&pckv, g_ckv);
    cudaGetSymbolAddress(&pkv,  g_kv);
    cudaGetSymbolAddress(&pao,  g_ao);
    float* q   = (float*)pq;
    float* ckv = (float*)pckv;
    float* kv  = (float*)pkv;
    float* ao  = (float*)pao;

    cudaFuncSetAttribute(attn_mma, cudaFuncAttributeMaxDynamicSharedMemorySize, ASMEM_BYTES);

    // 1) q = x @ Wq                          [8192,768] x [768,768]
    mma_gemm<<<dim3(CC / 128, MROWS / 128), 256>>>(x, Wq, nullptr, q, MROWS, CC, CC);
    // 2) ckv = x @ Wdown                     [8192,768] x [768,64]
    gemm_kernel<<<dim3(RR / GBN, MROWS / GBM), 256>>>(x, Wdown, nullptr, ckv, MROWS, RR, CC);
    // 3) layernorm
    ln_kernel<<<MROWS / 8, 256>>>(ckv, ln_g, ln_b);
    // 4) kv = ckv @ Wup                      [8192,64] x [64,1536]
    mma_gemm<<<dim3(KVW / 128, MROWS / 128), 256>>>(ckv, Wup, nullptr, kv, MROWS, KVW, RR);
    // 5) RoPE on q and on k-part of kv
    {
        int total = MROWS * HH * 32;
        int blocks = (total + 255) / 256;
        rope_kernel<<<blocks, 256>>>(q, CC);
        rope_kernel<<<blocks, 256>>>(kv, KVW);
    }
    // 6) attention
    attn_mma<<<dim3(TT / 64, HH, BB), 128, ASMEM_BYTES>>>(q, kv, ao);
    // 7) out = ao @ Wo + bo                  [8192,768] x [768,768]
    mma_gemm<<<dim3(CC / 128, MROWS / 128), 256>>>(ao, Wo, bo, out, MROWS, CC, CC);
}

// round 4
// speedup vs baseline: 7.2795x; 1.4239x over previous
#include <cuda_runtime.h>
#include <cuda_fp16.h>
#include <math.h>
#include <float.h>

// ---------------------------------------------------------------------------
// MLA forward. GEMMs: tf32 MMA. Attention: fp16 m16n8k16 MMA flash attention.
//   B=4, T=2048, C=768, H=12, D=64, R=64
// ---------------------------------------------------------------------------

#define BB 4
#define TT 2048
#define CC 768
#define HH 12
#define DD 64
#define RR 64
#define MROWS (BB * TT)            // 8192
#define KVW (2 * HH * DD)          // 1536
#define SCALE 0.125f               // D^-0.5

__device__ float g_q  [MROWS * CC];
__device__ float g_ckv[MROWS * RR];
__device__ float g_kv [MROWS * KVW];
__device__ float g_ao [MROWS * CC];

// ---------------------------------------------------------------------------
// helpers
// ---------------------------------------------------------------------------
__device__ __forceinline__ unsigned f2t(float f) {
    unsigned r;
    asm("cvt.rna.tf32.f32 %0, %1;" : "=r"(r) : "f"(f));
    return r;
}

__device__ __forceinline__ unsigned ph2(float lo, float hi) {
    __half2 h = __floats2half2_rn(lo, hi);
    return *(unsigned*)&h;
}

// tf32: D += A(16x8) * B(8x8)
__device__ __forceinline__ void mma8(float* c, const unsigned* a, const unsigned* b) {
    asm volatile(
        "mma.sync.aligned.m16n8k8.row.col.f32.tf32.tf32.f32 "
        "{%0,%1,%2,%3},{%4,%5,%6,%7},{%8,%9},{%0,%1,%2,%3};"
        : "+f"(c[0]), "+f"(c[1]), "+f"(c[2]), "+f"(c[3])
        : "r"(a[0]), "r"(a[1]), "r"(a[2]), "r"(a[3]), "r"(b[0]), "r"(b[1]));
}

// fp16: D += A(16x16) * B(16x8), fp32 accumulate
__device__ __forceinline__ void mma16(float* c, const unsigned* a, unsigned b0, unsigned b1) {
    asm volatile(
        "mma.sync.aligned.m16n8k16.row.col.f32.f16.f16.f32 "
        "{%0,%1,%2,%3},{%4,%5,%6,%7},{%8,%9},{%0,%1,%2,%3};"
        : "+f"(c[0]), "+f"(c[1]), "+f"(c[2]), "+f"(c[3])
        : "r"(a[0]), "r"(a[1]), "r"(a[2]), "r"(a[3]), "r"(b0), "r"(b1));
}

// ---------------------------------------------------------------------------
// tf32 MMA GEMM: C[M,N] = A[M,K] @ B[K,N] (+ bias). 128x128 tile, BK=16.
// ---------------------------------------------------------------------------
__global__ __launch_bounds__(256) void mma_gemm(
    const float* __restrict__ A, const float* __restrict__ B,
    const float* __restrict__ bias, float* __restrict__ C,
    int M, int N, int K)
{
    __shared__ unsigned As[128][20];
    __shared__ unsigned Bs[128][20];

    const int tid  = threadIdx.x;
    const int lane = tid & 31;
    const int w    = tid >> 5;
    const int g    = lane >> 2;
    const int tig  = lane & 3;
    const int wm   = (w & 3) * 32;
    const int wn   = (w >> 2) * 64;
    const int m0   = blockIdx.y * 128;
    const int n0   = blockIdx.x * 128;

    const int ar   = tid >> 1;
    const int ac   = (tid & 1) * 8;
    const int bk   = tid >> 4;
    const int bn16 = tid & 15;

    float4 pa0, pa1;
    float  pb[8];

    const float* Abase = A + (size_t)(m0 + ar) * K + ac;
    const float* Bbase = B + (size_t)bk * N + n0 + bn16;

    float acc[2][8][4];
#pragma unroll
    for (int mt = 0; mt < 2; ++mt)
#pragma unroll
        for (int nt = 0; nt < 8; ++nt)
#pragma unroll
            for (int i = 0; i < 4; ++i) acc[mt][nt][i] = 0.f;

    {
        const float* ap = Abase;
        pa0 = *(const float4*)ap; pa1 = *(const float4*)(ap + 4);
        const float* bp = Bbase;
#pragma unroll
        for (int j = 0; j < 8; ++j) pb[j] = bp[j * 16];
    }
    {
        uint4 v0 = make_uint4(f2t(pa0.x), f2t(pa0.y), f2t(pa0.z), f2t(pa0.w));
        uint4 v1 = make_uint4(f2t(pa1.x), f2t(pa1.y), f2t(pa1.z), f2t(pa1.w));
        *(uint4*)&As[ar][ac]     = v0;
        *(uint4*)&As[ar][ac + 4] = v1;
#pragma unroll
        for (int j = 0; j < 8; ++j) Bs[bn16 + j * 16][bk] = f2t(pb[j]);
    }
    __syncthreads();

    for (int kt = 16; ; kt += 16) {
        const bool more = (kt < K);
        if (more) {
            const float* ap = Abase + kt;
            pa0 = *(const float4*)ap; pa1 = *(const float4*)(ap + 4);
            const float* bp = Bbase + (size_t)kt * N;
#pragma unroll
            for (int j = 0; j < 8; ++j) pb[j] = bp[j * 16];
        }

#pragma unroll
        for (int kc = 0; kc < 2; ++kc) {
            const int kb = kc * 8;
            unsigned a[2][4], bf[8][2];
#pragma unroll
            for (int mt = 0; mt < 2; ++mt) {
                const int rb2 = wm + mt * 16;
                a[mt][0] = As[rb2 + g][kb + tig];
                a[mt][1] = As[rb2 + g + 8][kb + tig];
                a[mt][2] = As[rb2 + g][kb + tig + 4];
                a[mt][3] = As[rb2 + g + 8][kb + tig + 4];
            }
#pragma unroll
            for (int nt = 0; nt < 8; ++nt) {
                const int nb = wn + nt * 8;
                bf[nt][0] = Bs[nb + g][kb + tig];
                bf[nt][1] = Bs[nb + g][kb + tig + 4];
            }
#pragma unroll
            for (int mt = 0; mt < 2; ++mt)
#pragma unroll
                for (int nt = 0; nt < 8; ++nt)
                    mma8(acc[mt][nt], a[mt], bf[nt]);
        }

        if (!more) break;
        __syncthreads();
        {
            uint4 v0 = make_uint4(f2t(pa0.x), f2t(pa0.y), f2t(pa0.z), f2t(pa0.w));
            uint4 v1 = make_uint4(f2t(pa1.x), f2t(pa1.y), f2t(pa1.z), f2t(pa1.w));
            *(uint4*)&As[ar][ac]     = v0;
            *(uint4*)&As[ar][ac + 4] = v1;
#pragma unroll
            for (int j = 0; j < 8; ++j) Bs[bn16 + j * 16][bk] = f2t(pb[j]);
        }
        __syncthreads();
    }

#pragma unroll
    for (int mt = 0; mt < 2; ++mt) {
        const int r0 = m0 + wm + mt * 16 + g;
#pragma unroll
        for (int nt = 0; nt < 8; ++nt) {
            const int c0 = n0 + wn + nt * 8 + 2 * tig;
            float b0 = 0.f, b1 = 0.f;
            if (bias) { b0 = bias[c0]; b1 = bias[c0 + 1]; }
            *(float2*)(C + (size_t)r0 * N + c0) =
                make_float2(acc[mt][nt][0] + b0, acc[mt][nt][1] + b1);
            *(float2*)(C + (size_t)(r0 + 8) * N + c0) =
                make_float2(acc[mt][nt][2] + b0, acc[mt][nt][3] + b1);
        }
    }
}

// ---------------------------------------------------------------------------
// Scalar GEMM (Wdown: N=64)
// ---------------------------------------------------------------------------
#define GBM 64
#define GBN 64
#define GBK 16

__global__ __launch_bounds__(256) void gemm_kernel(
    const float* __restrict__ A, const float* __restrict__ B,
    const float* __restrict__ bias, float* __restrict__ C,
    int M, int N, int K)
{
    __shared__ float As[GBK][GBM + 4];
    __shared__ float Bs[GBK][GBN];

    const int tid = threadIdx.x;
    const int n0 = blockIdx.x * GBN;
    const int m0 = blockIdx.y * GBM;
    const int ty = tid >> 4, tx = tid & 15;
    const int ar = tid >> 2, ak = (tid & 3) * 4;
    const int bk = tid >> 4, bn = (tid & 15) * 4;

    const float* Aptr = A + (size_t)(m0 + ar) * K + ak;
    const float* Bptr = B + (size_t)bk * N + n0 + bn;

    float acc[4][4];
#pragma unroll
    for (int i = 0; i < 4; ++i)
#pragma unroll
        for (int j = 0; j < 4; ++j) acc[i][j] = 0.f;

    for (int kt = 0; kt < K; kt += GBK) {
        float4 a = *(const float4*)Aptr;
        Aptr += GBK;
        As[ak + 0][ar] = a.x; As[ak + 1][ar] = a.y;
        As[ak + 2][ar] = a.z; As[ak + 3][ar] = a.w;
        *(float4*)&Bs[bk][bn] = *(const float4*)Bptr;
        Bptr += (size_t)GBK * N;
        __syncthreads();
#pragma unroll
        for (int k = 0; k < GBK; ++k) {
            float4 av = *(const float4*)&As[k][ty * 4];
            float4 bv = *(const float4*)&Bs[k][tx * 4];
            acc[0][0] += av.x * bv.x; acc[0][1] += av.x * bv.y;
            acc[0][2] += av.x * bv.z; acc[0][3] += av.x * bv.w;
            acc[1][0] += av.y * bv.x; acc[1][1] += av.y * bv.y;
            acc[1][2] += av.y * bv.z; acc[1][3] += av.y * bv.w;
            acc[2][0] += av.z * bv.x; acc[2][1] += av.z * bv.y;
            acc[2][2] += av.z * bv.z; acc[2][3] += av.z * bv.w;
            acc[3][0] += av.w * bv.x; acc[3][1] += av.w * bv.y;
            acc[3][2] += av.w * bv.z; acc[3][3] += av.w * bv.w;
        }
        __syncthreads();
    }

    float4 bv4 = make_float4(0.f, 0.f, 0.f, 0.f);
    if (bias) bv4 = *(const float4*)(bias + n0 + tx * 4);
#pragma unroll
    for (int i = 0; i < 4; ++i) {
        float4 o;
        o.x = acc[i][0] + bv4.x; o.y = acc[i][1] + bv4.y;
        o.z = acc[i][2] + bv4.z; o.w = acc[i][3] + bv4.w;
        *(float4*)(C + (size_t)(m0 + ty * 4 + i) * N + n0 + tx * 4) = o;
    }
}

// ---------------------------------------------------------------------------
// LayerNorm over R=64 per row
// ---------------------------------------------------------------------------
__global__ __launch_bounds__(256) void ln_kernel(
    float* __restrict__ ckv, const float* __restrict__ g, const float* __restrict__ bpar)
{
    const int row  = blockIdx.x * 8 + (threadIdx.x >> 5);
    const int lane = threadIdx.x & 31;
    float* ptr = ckv + (size_t)row * RR;
    float v0 = ptr[lane], v1 = ptr[lane + 32];
    float s = v0 + v1, sq = v0 * v0 + v1 * v1;
#pragma unroll
    for (int o = 16; o; o >>= 1) {
        s  += __shfl_xor_sync(0xffffffffu, s,  o);
        sq += __shfl_xor_sync(0xffffffffu, sq, o);
    }
    float mean = s * (1.f / RR);
    float var  = sq * (1.f / RR) - mean * mean;
    float inv  = rsqrtf(var + 1e-5f);
    ptr[lane]      = (v0 - mean) * inv * g[lane]      + bpar[lane];
    ptr[lane + 32] = (v1 - mean) * inv * g[lane + 32] + bpar[lane + 32];
}

// ---------------------------------------------------------------------------
// RoPE (rotate-half), in-place
// ---------------------------------------------------------------------------
__global__ __launch_bounds__(256) void rope_kernel(float* __restrict__ ptr, int rowStride)
{
    int idx = blockIdx.x * blockDim.x + threadIdx.x;
    if (idx >= MROWS * HH * 32) return;
    int i   = idx & 31;
    int h   = (idx >> 5) % HH;
    int row = idx / (HH * 32);
    int t   = row & (TT - 1);

    // 10000^(-i/32) = 2^(-i/32 * log2(10000))
    float inv = exp2f(-(float)i * (13.287712379549449f / 32.f));
    float ang = (float)t * inv;
    float sn, cs;
    sincosf(ang, &sn, &cs);

    float* base = ptr + (size_t)row * rowStride + h * DD;
    float x0 = base[i], x1 = base[i + 32];
    base[i]      = x0 * cs - x1 * sn;
    base[i + 32] = x1 * cs + x0 * sn;
}

// ---------------------------------------------------------------------------
// Causal flash attention, fp16 m16n8k16 MMA, fp32 accumulate.
// grid = (T/64, H, B) with q-tile index REVERSED (long rows first).
// block = 128 (4 warps); warp w owns q rows [w*16, w*16+16).
// Smem (half2 words):
//   Qp[64][36]: (Q[r][2j],Q[r][2j+1])         — A-fragment pairs along d
//   Kp[64][36]: (K[s][2j],K[s][2j+1])         — B-fragment pairs along d
//   Vp[32][72]: (V[2s][d],V[2s+1][d])         — B-fragment pairs along s
// P never goes to smem: fp16 accumulator layout == A-operand layout.
// ---------------------------------------------------------------------------
__global__ __launch_bounds__(128) void attn_f16(
    const float* __restrict__ q, const float* __restrict__ kv, float* __restrict__ ao)
{
    __shared__ unsigned Qp[64][36];
    __shared__ unsigned Kp[64][36];
    __shared__ unsigned Vp[32][72];

    const int tid  = threadIdx.x;
    const int lane = tid & 31;
    const int w    = tid >> 5;
    const int g    = lane >> 2;
    const int tig  = lane & 3;
    const int qi   = (gridDim.x - 1) - blockIdx.x;   // reversed: big work first
    const int i0   = qi * 64;
    const int h    = blockIdx.y;
    const int b    = blockIdx.z;
    const int rb   = w * 16;

    // --- load Q tile (scaled fp16 pairs) ---
    {
        const int r  = tid >> 1;
        const int hh = (tid & 1) * 32;
        const float* src = q + (size_t)(b * TT + i0 + r) * CC + h * DD + hh;
#pragma unroll
        for (int j = 0; j < 32; j += 4) {
            float4 v = *(const float4*)(src + j);
            Qp[r][(hh + j) >> 1]       = ph2(v.x * SCALE, v.y * SCALE);
            Qp[r][((hh + j) >> 1) + 1] = ph2(v.z * SCALE, v.w * SCALE);
        }
    }
    __syncthreads();

    // Q fragments: 4 k-chunks of 16 over D=64
    unsigned qa[4][4];
#pragma unroll
    for (int kk = 0; kk < 4; ++kk) {
        qa[kk][0] = Qp[rb + g][kk * 8 + tig];
        qa[kk][1] = Qp[rb + g + 8][kk * 8 + tig];
        qa[kk][2] = Qp[rb + g][kk * 8 + tig + 4];
        qa[kk][3] = Qp[rb + g + 8][kk * 8 + tig + 4];
    }

    float mr0 = -INFINITY, mr1 = -INFINITY, l0 = 0.f, l1 = 0.f;
    float oacc[8][4];
#pragma unroll
    for (int nt = 0; nt < 8; ++nt)
#pragma unroll
        for (int i = 0; i < 4; ++i) oacc[nt][i] = 0.f;

    const int ntile = qi + 1;
    for (int jt = 0; jt < ntile; ++jt) {
        const int j0 = jt * 64;
        __syncthreads();   // prev tile's K/V reads complete

        // --- load K tile (pairs along d) ---
        {
            const int r  = tid >> 1;
            const int hh = (tid & 1) * 32;
            const float* kp = kv + (size_t)(b * TT + j0 + r) * KVW + h * DD + hh;
#pragma unroll
            for (int j = 0; j < 32; j += 4) {
                float4 v = *(const float4*)(kp + j);
                Kp[r][(hh + j) >> 1]       = ph2(v.x, v.y);
                Kp[r][((hh + j) >> 1) + 1] = ph2(v.z, v.w);
            }
        }
        // --- load V tile (pairs along s) ---
        {
            const int s2 = tid >> 2;
            const int dq = (tid & 3) * 16;
            const float* va = kv + (size_t)(b * TT + j0 + 2 * s2) * KVW + (HH + h) * DD + dq;
            const float* vb = va + KVW;
#pragma unroll
            for (int j = 0; j < 16; j += 4) {
                float4 A = *(const float4*)(va + j);
                float4 Bv = *(const float4*)(vb + j);
                uint4 pk = make_uint4(ph2(A.x, Bv.x), ph2(A.y, Bv.y),
                                      ph2(A.z, Bv.z), ph2(A.w, Bv.w));
                *(uint4*)&Vp[s2][dq + j] = pk;
            }
        }
        __syncthreads();

        // --- S = Q K^T  (warp: 16 x 64) ---
        float sacc[8][4];
#pragma unroll
        for (int nt = 0; nt < 8; ++nt)
#pragma unroll
            for (int i = 0; i < 4; ++i) sacc[nt][i] = 0.f;
#pragma unroll
        for (int kk = 0; kk < 4; ++kk) {
#pragma unroll
            for (int nt = 0; nt < 8; ++nt) {
                unsigned b0 = Kp[nt * 8 + g][kk * 8 + tig];
                unsigned b1 = Kp[nt * 8 + g][kk * 8 + tig + 4];
                mma16(sacc[nt], qa[kk], b0, b1);
            }
        }

        // --- causal mask (diagonal tile only) ---
        if (jt == ntile - 1) {
            const int r0g = i0 + rb + g, r1g = r0g + 8;
#pragma unroll
            for (int nt = 0; nt < 8; ++nt) {
                const int c = j0 + nt * 8 + 2 * tig;
                if (c > r0g)     sacc[nt][0] = -INFINITY;
                if (c + 1 > r0g) sacc[nt][1] = -INFINITY;
                if (c > r1g)     sacc[nt][2] = -INFINITY;
                if (c + 1 > r1g) sacc[nt][3] = -INFINITY;
            }
        }

        // --- online softmax ---
        float tm0 = -INFINITY, tm1 = -INFINITY;
#pragma unroll
        for (int nt = 0; nt < 8; ++nt) {
            tm0 = fmaxf(tm0, fmaxf(sacc[nt][0], sacc[nt][1]));
            tm1 = fmaxf(tm1, fmaxf(sacc[nt][2], sacc[nt][3]));
        }
        tm0 = fmaxf(tm0, __shfl_xor_sync(0xffffffffu, tm0, 1));
        tm0 = fmaxf(tm0, __shfl_xor_sync(0xffffffffu, tm0, 2));
        tm1 = fmaxf(tm1, __shfl_xor_sync(0xffffffffu, tm1, 1));
        tm1 = fmaxf(tm1, __shfl_xor_sync(0xffffffffu, tm1, 2));

        const float mn0 = fmaxf(mr0, tm0), mn1 = fmaxf(mr1, tm1);
        const float al0 = __expf(mr0 - mn0), al1 = __expf(mr1 - mn1);
        float s0 = 0.f, s1 = 0.f;
#pragma unroll
        for (int nt = 0; nt < 8; ++nt) {
            sacc[nt][0] = __expf(sacc[nt][0] - mn0);
            sacc[nt][1] = __expf(sacc[nt][1] - mn0);
            sacc[nt][2] = __expf(sacc[nt][2] - mn1);
            sacc[nt][3] = __expf(sacc[nt][3] - mn1);
            s0 += sacc[nt][0] + sacc[nt][1];
            s1 += sacc[nt][2] + sacc[nt][3];
        }
        s0 += __shfl_xor_sync(0xffffffffu, s0, 1);
        s0 += __shfl_xor_sync(0xffffffffu, s0, 2);
        s1 += __shfl_xor_sync(0xffffffffu, s1, 1);
        s1 += __shfl_xor_sync(0xffffffffu, s1, 2);
        l0 = l0 * al0 + s0;
        l1 = l1 * al1 + s1;
        mr0 = mn0; mr1 = mn1;
#pragma unroll
        for (int nt = 0; nt < 8; ++nt) {
            oacc[nt][0] *= al0; oacc[nt][1] *= al0;
            oacc[nt][2] *= al1; oacc[nt][3] *= al1;
        }

        // --- pack P to fp16 (register-resident: acc layout == A layout) ---
        unsigned pfr[4][4];
#pragma unroll
        for (int kk = 0; kk < 4; ++kk) {
            pfr[kk][0] = ph2(sacc[2 * kk][0],     sacc[2 * kk][1]);
            pfr[kk][1] = ph2(sacc[2 * kk][2],     sacc[2 * kk][3]);
            pfr[kk][2] = ph2(sacc[2 * kk + 1][0], sacc[2 * kk + 1][1]);
            pfr[kk][3] = ph2(sacc[2 * kk + 1][2], sacc[2 * kk + 1][3]);
        }

        // --- O += P V ---
#pragma unroll
        for (int kk = 0; kk < 4; ++kk) {
#pragma unroll
            for (int nt = 0; nt < 8; ++nt) {
                unsigned b0 = Vp[kk * 8 + tig][nt * 8 + g];
                unsigned b1 = Vp[kk * 8 + tig + 4][nt * 8 + g];
                mma16(oacc[nt], pfr[kk], b0, b1);
            }
        }
    }

    // --- finalize ---
    const float inv0 = 1.f / l0, inv1 = 1.f / l1;
    float* dst0 = ao + (size_t)(b * TT + i0 + rb + g) * CC + h * DD;
    float* dst1 = dst0 + (size_t)8 * CC;
#pragma unroll
    for (int nt = 0; nt < 8; ++nt) {
        const int c = nt * 8 + 2 * tig;
        *(float2*)(dst0 + c) = make_float2(oacc[nt][0] * inv0, oacc[nt][1] * inv0);
        *(float2*)(dst1 + c) = make_float2(oacc[nt][2] * inv1, oacc[nt][3] * inv1);
    }
}

// ---------------------------------------------------------------------------
// Launch
// ---------------------------------------------------------------------------
extern "C" void kernel_launch(void* const* d_in, const int* in_sizes, int n_in,
                              void* d_out, int out_size)
{
    const float* x     = (const float*)d_in[0];
    const float* Wq    = (const float*)d_in[1];
    const float* Wdown = (const float*)d_in[2];
    const float* ln_g  = (const float*)d_in[3];
    const float* ln_b  = (const float*)d_in[4];
    const float* Wup   = (const float*)d_in[5];
    const float* Wo    = (const float*)d_in[6];
    const float* bo    = (const float*)d_in[7];
    float* out = (float*)d_out;

    void *pq, *pckv, *pkv, *pao;
    cudaGetSymbolAddress(&pq,   g_q);
    cudaGetSymbolAddress(&pckv, g_ckv);
    cudaGetSymbolAddress(&pkv,  g_kv);
    cudaGetSymbolAddress(&pao,  g_ao);
    float* q   = (float*)pq;
    float* ckv = (float*)pckv;
    float* kv  = (float*)pkv;
    float* ao  = (float*)pao;

    // 1) q = x @ Wq
    mma_gemm<<<dim3(CC / 128, MROWS / 128), 256>>>(x, Wq, nullptr, q, MROWS, CC, CC);
    // 2) ckv = x @ Wdown
    gemm_kernel<<<dim3(RR / GBN, MROWS / GBM), 256>>>(x, Wdown, nullptr, ckv, MROWS, RR, CC);
    // 3) layernorm
    ln_kernel<<<MROWS / 8, 256>>>(ckv, ln_g, ln_b);
    // 4) kv = ckv @ Wup
    mma_gemm<<<dim3(KVW / 128, MROWS / 128), 256>>>(ckv, Wup, nullptr, kv, MROWS, KVW, RR);
    // 5) RoPE
    {
        int total = MROWS * HH * 32;
        int blocks = (total + 255) / 256;
        rope_kernel<<<blocks, 256>>>(q, CC);
        rope_kernel<<<blocks, 256>>>(kv, KVW);
    }
    // 6) attention (fp16 MMA)
    attn_f16<<<dim3(TT / 64, HH, BB), 128>>>(q, kv, ao);
    // 7) out = ao @ Wo + bo
    mma_gemm<<<dim3(CC / 128, MROWS / 128), 256>>>(ao, Wo, bo, out, MROWS, CC, CC);
}

// round 5
// speedup vs baseline: 10.4347x; 1.4334x over previous
#include <cuda_runtime.h>
#include <cuda_fp16.h>
#include <math.h>
#include <float.h>

// ---------------------------------------------------------------------------
// MLA forward. All matmuls on fp16 m16n8k16 MMA (fp32 accumulate).
//   B=4, T=2048, C=768, H=12, D=64, R=64
// ---------------------------------------------------------------------------

#define BB 4
#define TT 2048
#define CC 768
#define HH 12
#define DD 64
#define RR 64
#define MROWS (BB * TT)            // 8192
#define KVW (2 * HH * DD)          // 1536
#define SCALE 0.125f               // D^-0.5
#define LOG2E 1.4426950408889634f

__device__ float g_q  [MROWS * CC];
__device__ float g_ckv[MROWS * RR];
__device__ float g_kv [MROWS * KVW];
__device__ float g_ao [MROWS * CC];

// ---------------------------------------------------------------------------
// helpers
// ---------------------------------------------------------------------------
__device__ __forceinline__ unsigned ph2(float lo, float hi) {
    __half2 h = __floats2half2_rn(lo, hi);
    return *(unsigned*)&h;
}

// fp16: D += A(16x16) * B(16x8), fp32 accumulate
__device__ __forceinline__ void mma16(float* c, const unsigned* a, unsigned b0, unsigned b1) {
    asm volatile(
        "mma.sync.aligned.m16n8k16.row.col.f32.f16.f16.f32 "
        "{%0,%1,%2,%3},{%4,%5,%6,%7},{%8,%9},{%0,%1,%2,%3};"
        : "+f"(c[0]), "+f"(c[1]), "+f"(c[2]), "+f"(c[3])
        : "r"(a[0]), "r"(a[1]), "r"(a[2]), "r"(a[3]), "r"(b0), "r"(b1));
}

// ---------------------------------------------------------------------------
// fp16 MMA GEMM: C[M,N] = A[M,K] @ B[K,N] (+ bias).
// Block tile 128 x BN, BK=16, 256 threads (8 warps: 4m x 2n).
// Smem: Ah[m][k/2] half2 words (stride 12), Bh[kpair][n] (stride BN+8).
// Requires M%128==0, N%BN==0, K%16==0. BN in {128, 64}.
// ---------------------------------------------------------------------------
template<int BN>
__global__ __launch_bounds__(256) void hgemm(
    const float* __restrict__ A, const float* __restrict__ B,
    const float* __restrict__ bias, float* __restrict__ C,
    int M, int N, int K)
{
    constexpr int NT = BN / 16;             // per-warp n-tiles: 8 or 4
    __shared__ unsigned Ah[128][12];        // 8 words + 4 pad
    __shared__ unsigned Bh[8][BN + 8];

    const int tid  = threadIdx.x;
    const int lane = tid & 31;
    const int w    = tid >> 5;
    const int g    = lane >> 2;
    const int tig  = lane & 3;
    const int wm   = (w & 3) * 32;
    const int wn   = (w >> 2) * (BN / 2);
    const int m0   = blockIdx.y * 128;
    const int n0   = blockIdx.x * BN;

    const int ar   = tid >> 1;              // A row 0..127
    const int ac2  = (tid & 1) * 4;         // A word offset 0 or 4 (k/2)

    const int bn4  = (BN == 128) ? (tid & 31) * 4 : (tid & 15) * 4;
    const int kp   = (BN == 128) ? (tid >> 5) : (tid >> 4);
    const bool bact = (BN == 128) || (tid < 128);

    const float* Abase = A + (size_t)(m0 + ar) * K + ac2 * 2;
    const float* B0 = B + (size_t)(2 * kp) * N + n0 + bn4;
    const float* B1 = B0 + N;

    float acc[2][NT][4];
#pragma unroll
    for (int mt = 0; mt < 2; ++mt)
#pragma unroll
        for (int nt = 0; nt < NT; ++nt)
#pragma unroll
            for (int i = 0; i < 4; ++i) acc[mt][nt][i] = 0.f;

    float4 pa0, pa1;
    float4 pb0 = make_float4(0, 0, 0, 0), pb1 = make_float4(0, 0, 0, 0);

    // prologue: tile 0
    pa0 = *(const float4*)Abase;
    pa1 = *(const float4*)(Abase + 4);
    if (bact) { pb0 = *(const float4*)B0; pb1 = *(const float4*)B1; }
    {
        uint4 av = make_uint4(ph2(pa0.x, pa0.y), ph2(pa0.z, pa0.w),
                              ph2(pa1.x, pa1.y), ph2(pa1.z, pa1.w));
        *(uint4*)&Ah[ar][ac2] = av;
        if (bact) {
            uint4 bv = make_uint4(ph2(pb0.x, pb1.x), ph2(pb0.y, pb1.y),
                                  ph2(pb0.z, pb1.z), ph2(pb0.w, pb1.w));
            *(uint4*)&Bh[kp][bn4] = bv;
        }
    }
    __syncthreads();

    for (int kt = 16; ; kt += 16) {
        const bool more = (kt < K);
        if (more) {
            const float* ap = Abase + kt;
            pa0 = *(const float4*)ap;
            pa1 = *(const float4*)(ap + 4);
            if (bact) {
                const float* bp = B0 + (size_t)kt * N;
                pb0 = *(const float4*)bp;
                pb1 = *(const float4*)(bp + N);
            }
        }

        // --- MMA on current tile (one k16 chunk) ---
        unsigned a[2][4];
#pragma unroll
        for (int mt = 0; mt < 2; ++mt) {
            const int rb = wm + mt * 16;
            a[mt][0] = Ah[rb + g][tig];
            a[mt][1] = Ah[rb + g + 8][tig];
            a[mt][2] = Ah[rb + g][tig + 4];
            a[mt][3] = Ah[rb + g + 8][tig + 4];
        }
#pragma unroll
        for (int nt = 0; nt < NT; ++nt) {
            const int nb = wn + nt * 8 + g;
            unsigned b0 = Bh[tig][nb];
            unsigned b1 = Bh[tig + 4][nb];
#pragma unroll
            for (int mt = 0; mt < 2; ++mt)
                mma16(acc[mt][nt], a[mt], b0, b1);
        }

        if (!more) break;
        __syncthreads();
        {
            uint4 av = make_uint4(ph2(pa0.x, pa0.y), ph2(pa0.z, pa0.w),
                                  ph2(pa1.x, pa1.y), ph2(pa1.z, pa1.w));
            *(uint4*)&Ah[ar][ac2] = av;
            if (bact) {
                uint4 bv = make_uint4(ph2(pb0.x, pb1.x), ph2(pb0.y, pb1.y),
                                      ph2(pb0.z, pb1.z), ph2(pb0.w, pb1.w));
                *(uint4*)&Bh[kp][bn4] = bv;
            }
        }
        __syncthreads();
    }

    // epilogue
#pragma unroll
    for (int mt = 0; mt < 2; ++mt) {
        const int r0 = m0 + wm + mt * 16 + g;
#pragma unroll
        for (int nt = 0; nt < NT; ++nt) {
            const int c0 = n0 + wn + nt * 8 + 2 * tig;
            float b0 = 0.f, b1 = 0.f;
            if (bias) { b0 = bias[c0]; b1 = bias[c0 + 1]; }
            *(float2*)(C + (size_t)r0 * N + c0) =
                make_float2(acc[mt][nt][0] + b0, acc[mt][nt][1] + b1);
            *(float2*)(C + (size_t)(r0 + 8) * N + c0) =
                make_float2(acc[mt][nt][2] + b0, acc[mt][nt][3] + b1);
        }
    }
}

// ---------------------------------------------------------------------------
// LayerNorm over R=64 per row
// ---------------------------------------------------------------------------
__global__ __launch_bounds__(256) void ln_kernel(
    float* __restrict__ ckv, const float* __restrict__ g, const float* __restrict__ bpar)
{
    const int row  = blockIdx.x * 8 + (threadIdx.x >> 5);
    const int lane = threadIdx.x & 31;
    float* ptr = ckv + (size_t)row * RR;
    float v0 = ptr[lane], v1 = ptr[lane + 32];
    float s = v0 + v1, sq = v0 * v0 + v1 * v1;
#pragma unroll
    for (int o = 16; o; o >>= 1) {
        s  += __shfl_xor_sync(0xffffffffu, s,  o);
        sq += __shfl_xor_sync(0xffffffffu, sq, o);
    }
    float mean = s * (1.f / RR);
    float var  = sq * (1.f / RR) - mean * mean;
    float inv  = rsqrtf(var + 1e-5f);
    ptr[lane]      = (v0 - mean) * inv * g[lane]      + bpar[lane];
    ptr[lane + 32] = (v1 - mean) * inv * g[lane + 32] + bpar[lane + 32];
}

// ---------------------------------------------------------------------------
// RoPE (rotate-half), in-place
// ---------------------------------------------------------------------------
__global__ __launch_bounds__(256) void rope_kernel(float* __restrict__ ptr, int rowStride)
{
    int idx = blockIdx.x * blockDim.x + threadIdx.x;
    if (idx >= MROWS * HH * 32) return;
    int i   = idx & 31;
    int h   = (idx >> 5) % HH;
    int row = idx / (HH * 32);
    int t   = row & (TT - 1);

    float inv = exp2f(-(float)i * (13.287712379549449f / 32.f));
    float ang = (float)t * inv;
    float sn, cs;
    sincosf(ang, &sn, &cs);

    float* base = ptr + (size_t)row * rowStride + h * DD;
    float x0 = base[i], x1 = base[i + 32];
    base[i]      = x0 * cs - x1 * sn;
    base[i + 32] = x1 * cs + x0 * sn;
}

// ---------------------------------------------------------------------------
// Causal flash attention, fp16 m16n8k16 MMA, fp32 accumulate, base-2 softmax.
// grid = (T/128, H, B), q-tile index reversed. block = 256 (8 warps).
// Warp w owns q rows [w*16, w*16+16) of a 128-row q tile; KV tile = 64.
// Smem (half2 words): Qp[128][36], Kp[64][36], Vp[32][72].
// ---------------------------------------------------------------------------
__global__ __launch_bounds__(256, 2) void attn_f16(
    const float* __restrict__ q, const float* __restrict__ kv, float* __restrict__ ao)
{
    __shared__ unsigned Qp[128][36];
    __shared__ unsigned Kp[64][36];
    __shared__ unsigned Vp[32][72];

    const int tid  = threadIdx.x;
    const int lane = tid & 31;
    const int w    = tid >> 5;
    const int g    = lane >> 2;
    const int tig  = lane & 3;
    const int qi   = (gridDim.x - 1) - blockIdx.x;   // big tiles first
    const int i0   = qi * 128;
    const int h    = blockIdx.y;
    const int b    = blockIdx.z;
    const int rb   = w * 16;
    const int row_min = i0 + rb;
    const int row_max = row_min + 15;

    // --- load Q tile (scaled by SCALE*log2(e), fp16 pairs) ---
    {
        const float qsc = SCALE * LOG2E;
        const int r  = tid >> 1;
        const int hh = (tid & 1) * 32;
        const float* src = q + (size_t)(b * TT + i0 + r) * CC + h * DD + hh;
#pragma unroll
        for (int j = 0; j < 32; j += 4) {
            float4 v = *(const float4*)(src + j);
            Qp[r][(hh + j) >> 1]       = ph2(v.x * qsc, v.y * qsc);
            Qp[r][((hh + j) >> 1) + 1] = ph2(v.z * qsc, v.w * qsc);
        }
    }
    __syncthreads();

    // Q fragments: 4 k-chunks of 16 over D=64
    unsigned qa[4][4];
#pragma unroll
    for (int kk = 0; kk < 4; ++kk) {
        qa[kk][0] = Qp[rb + g][kk * 8 + tig];
        qa[kk][1] = Qp[rb + g + 8][kk * 8 + tig];
        qa[kk][2] = Qp[rb + g][kk * 8 + tig + 4];
        qa[kk][3] = Qp[rb + g + 8][kk * 8 + tig + 4];
    }

    float mr0 = -INFINITY, mr1 = -INFINITY, l0 = 0.f, l1 = 0.f;
    float oacc[8][4];
#pragma unroll
    for (int nt = 0; nt < 8; ++nt)
#pragma unroll
        for (int i = 0; i < 4; ++i) oacc[nt][i] = 0.f;

    const int ntile = 2 * qi + 2;
    for (int jt = 0; jt < ntile; ++jt) {
        const int j0 = jt * 64;
        __syncthreads();   // prev tile's K/V reads complete

        // --- load K tile (pairs along d): 256 thr, 64 rows ---
        {
            const int r  = tid >> 2;
            const int hh = (tid & 3) * 16;
            const float* kp = kv + (size_t)(b * TT + j0 + r) * KVW + h * DD + hh;
#pragma unroll
            for (int j = 0; j < 16; j += 4) {
                float4 v = *(const float4*)(kp + j);
                Kp[r][(hh + j) >> 1]       = ph2(v.x, v.y);
                Kp[r][((hh + j) >> 1) + 1] = ph2(v.z, v.w);
            }
        }
        // --- load V tile (pairs along s) ---
        {
            const int s2 = tid >> 3;
            const int dq = (tid & 7) * 8;
            const float* va = kv + (size_t)(b * TT + j0 + 2 * s2) * KVW + (HH + h) * DD + dq;
            const float* vb = va + KVW;
            float4 A0 = *(const float4*)va;
            float4 A1 = *(const float4*)(va + 4);
            float4 B0 = *(const float4*)vb;
            float4 B1 = *(const float4*)(vb + 4);
            uint4 p0 = make_uint4(ph2(A0.x, B0.x), ph2(A0.y, B0.y),
                                  ph2(A0.z, B0.z), ph2(A0.w, B0.w));
            uint4 p1 = make_uint4(ph2(A1.x, B1.x), ph2(A1.y, B1.y),
                                  ph2(A1.z, B1.z), ph2(A1.w, B1.w));
            *(uint4*)&Vp[s2][dq]     = p0;
            *(uint4*)&Vp[s2][dq + 4] = p1;
        }
        __syncthreads();

        if (j0 > row_max) continue;   // fully masked for this warp

        // --- S = Q K^T  (warp: 16 x 64), scores already in base-2 domain ---
        float sacc[8][4];
#pragma unroll
        for (int nt = 0; nt < 8; ++nt)
#pragma unroll
            for (int i = 0; i < 4; ++i) sacc[nt][i] = 0.f;
#pragma unroll
        for (int kk = 0; kk < 4; ++kk) {
#pragma unroll
            for (int nt = 0; nt < 8; ++nt) {
                unsigned b0 = Kp[nt * 8 + g][kk * 8 + tig];
                unsigned b1 = Kp[nt * 8 + g][kk * 8 + tig + 4];
                mma16(sacc[nt], qa[kk], b0, b1);
            }
        }

        // --- causal mask (partial tile only) ---
        if (j0 + 63 > row_min) {
            const int r0g = row_min + g, r1g = r0g + 8;
#pragma unroll
            for (int nt = 0; nt < 8; ++nt) {
                const int c = j0 + nt * 8 + 2 * tig;
                if (c > r0g)     sacc[nt][0] = -INFINITY;
                if (c + 1 > r0g) sacc[nt][1] = -INFINITY;
                if (c > r1g)     sacc[nt][2] = -INFINITY;
                if (c + 1 > r1g) sacc[nt][3] = -INFINITY;
            }
        }

        // --- online softmax (base 2) ---
        float tm0 = -INFINITY, tm1 = -INFINITY;
#pragma unroll
        for (int nt = 0; nt < 8; ++nt) {
            tm0 = fmaxf(tm0, fmaxf(sacc[nt][0], sacc[nt][1]));
            tm1 = fmaxf(tm1, fmaxf(sacc[nt][2], sacc[nt][3]));
        }
        tm0 = fmaxf(tm0, __shfl_xor_sync(0xffffffffu, tm0, 1));
        tm0 = fmaxf(tm0, __shfl_xor_sync(0xffffffffu, tm0, 2));
        tm1 = fmaxf(tm1, __shfl_xor_sync(0xffffffffu, tm1, 1));
        tm1 = fmaxf(tm1, __shfl_xor_sync(0xffffffffu, tm1, 2));

        const float mn0 = fmaxf(mr0, tm0), mn1 = fmaxf(mr1, tm1);
        const float al0 = exp2f(mr0 - mn0), al1 = exp2f(mr1 - mn1);
        float s0 = 0.f, s1 = 0.f;
#pragma unroll
        for (int nt = 0; nt < 8; ++nt) {
            sacc[nt][0] = exp2f(sacc[nt][0] - mn0);
            sacc[nt][1] = exp2f(sacc[nt][1] - mn0);
            sacc[nt][2] = exp2f(sacc[nt][2] - mn1);
            sacc[nt][3] = exp2f(sacc[nt][3] - mn1);
            s0 += sacc[nt][0] + sacc[nt][1];
            s1 += sacc[nt][2] + sacc[nt][3];
        }
        s0 += __shfl_xor_sync(0xffffffffu, s0, 1);
        s0 += __shfl_xor_sync(0xffffffffu, s0, 2);
        s1 += __shfl_xor_sync(0xffffffffu, s1, 1);
        s1 += __shfl_xor_sync(0xffffffffu, s1, 2);
        l0 = l0 * al0 + s0;
        l1 = l1 * al1 + s1;
        mr0 = mn0; mr1 = mn1;
#pragma unroll
        for (int nt = 0; nt < 8; ++nt) {
            oacc[nt][0] *= al0; oacc[nt][1] *= al0;
            oacc[nt][2] *= al1; oacc[nt][3] *= al1;
        }

        // --- pack P to fp16 (register-resident) ---
        unsigned pfr[4][4];
#pragma unroll
        for (int kk = 0; kk < 4; ++kk) {
            pfr[kk][0] = ph2(sacc[2 * kk][0],     sacc[2 * kk][1]);
            pfr[kk][1] = ph2(sacc[2 * kk][2],     sacc[2 * kk][3]);
            pfr[kk][2] = ph2(sacc[2 * kk + 1][0], sacc[2 * kk + 1][1]);
            pfr[kk][3] = ph2(sacc[2 * kk + 1][2], sacc[2 * kk + 1][3]);
        }

        // --- O += P V ---
#pragma unroll
        for (int kk = 0; kk < 4; ++kk) {
#pragma unroll
            for (int nt = 0; nt < 8; ++nt) {
                unsigned b0 = Vp[kk * 8 + tig][nt * 8 + g];
                unsigned b1 = Vp[kk * 8 + tig + 4][nt * 8 + g];
                mma16(oacc[nt], pfr[kk], b0, b1);
            }
        }
    }

    // --- finalize ---
    const float inv0 = 1.f / l0, inv1 = 1.f / l1;
    float* dst0 = ao + (size_t)(b * TT + i0 + rb + g) * CC + h * DD;
    float* dst1 = dst0 + (size_t)8 * CC;
#pragma unroll
    for (int nt = 0; nt < 8; ++nt) {
        const int c = nt * 8 + 2 * tig;
        *(float2*)(dst0 + c) = make_float2(oacc[nt][0] * inv0, oacc[nt][1] * inv0);
        *(float2*)(dst1 + c) = make_float2(oacc[nt][2] * inv1, oacc[nt][3] * inv1);
    }
}

// ---------------------------------------------------------------------------
// Launch
// ---------------------------------------------------------------------------
extern "C" void kernel_launch(void* const* d_in, const int* in_sizes, int n_in,
                              void* d_out, int out_size)
{
    const float* x     = (const float*)d_in[0];
    const float* Wq    = (const float*)d_in[1];
    const float* Wdown = (const float*)d_in[2];
    const float* ln_g  = (const float*)d_in[3];
    const float* ln_b  = (const float*)d_in[4];
    const float* Wup   = (const float*)d_in[5];
    const float* Wo    = (const float*)d_in[6];
    const float* bo    = (const float*)d_in[7];
    float* out = (float*)d_out;

    void *pq, *pckv, *pkv, *pao;
    cudaGetSymbolAddress(&pq,   g_q);
    cudaGetSymbolAddress(&pckv, g_ckv);
    cudaGetSymbolAddress(&pkv,  g_kv);
    cudaGetSymbolAddress(&pao,  g_ao);
    float* q   = (float*)pq;
    float* ckv = (float*)pckv;
    float* kv  = (float*)pkv;
    float* ao  = (float*)pao;

    // 1) q = x @ Wq
    hgemm<128><<<dim3(CC / 128, MROWS / 128), 256>>>(x, Wq, nullptr, q, MROWS, CC, CC);
    // 2) ckv = x @ Wdown
    hgemm<64><<<dim3(RR / 64, MROWS / 128), 256>>>(x, Wdown, nullptr, ckv, MROWS, RR, CC);
    // 3) layernorm
    ln_kernel<<<MROWS / 8, 256>>>(ckv, ln_g, ln_b);
    // 4) kv = ckv @ Wup
    hgemm<128><<<dim3(KVW / 128, MROWS / 128), 256>>>(ckv, Wup, nullptr, kv, MROWS, KVW, RR);
    // 5) RoPE
    {
        int total = MROWS * HH * 32;
        int blocks = (total + 255) / 256;
        rope_kernel<<<blocks, 256>>>(q, CC);
        rope_kernel<<<blocks, 256>>>(kv, KVW);
    }
    // 6) attention (fp16 MMA, 128-row q tiles)
    attn_f16<<<dim3(TT / 128, HH, BB), 256>>>(q, kv, ao);
    // 7) out = ao @ Wo + bo
    hgemm<128><<<dim3(CC / 128, MROWS / 128), 256>>>(ao, Wo, bo, out, MROWS, CC, CC);
}

// round 6
// speedup vs baseline: 14.9342x; 1.4312x over previous
#include <cuda_runtime.h>
#include <cuda_fp16.h>
#include <math.h>
#include <float.h>

// ---------------------------------------------------------------------------
// MLA forward, full fp16 dataflow (fp32 accumulate everywhere).
//   B=4, T=2048, C=768, H=12, D=64, R=64
// ---------------------------------------------------------------------------

#define BB 4
#define TT 2048
#define CC 768
#define HH 12
#define DD 64
#define RR 64
#define MROWS (BB * TT)            // 8192
#define KVW (2 * HH * DD)          // 1536
#define SCALE 0.125f
#define LOG2E 1.4426950408889634f

// Scratch (device globals)
__device__ __half g_xh  [MROWS * CC];
__device__ __half g_q16 [MROWS * CC];
__device__ float  g_ckv [MROWS * RR];
__device__ __half g_ckvh[MROWS * RR];
__device__ __half g_kv16[MROWS * KVW];
__device__ __half g_ao16[MROWS * CC];
__device__ __half g_wq  [CC * HH * DD];
__device__ __half g_wdn [CC * RR];
__device__ __half g_wup [RR * KVW];
__device__ __half g_wo  [HH * DD * CC];

// ---------------------------------------------------------------------------
// helpers
// ---------------------------------------------------------------------------
__device__ __forceinline__ unsigned ph2(float lo, float hi) {
    __half2 h = __floats2half2_rn(lo, hi);
    return *(unsigned*)&h;
}

__device__ __forceinline__ void mma16(float* c, const unsigned* a, unsigned b0, unsigned b1) {
    asm volatile(
        "mma.sync.aligned.m16n8k16.row.col.f32.f16.f16.f32 "
        "{%0,%1,%2,%3},{%4,%5,%6,%7},{%8,%9},{%0,%1,%2,%3};"
        : "+f"(c[0]), "+f"(c[1]), "+f"(c[2]), "+f"(c[3])
        : "r"(a[0]), "r"(a[1]), "r"(a[2]), "r"(a[3]), "r"(b0), "r"(b1));
}

__device__ __forceinline__ void ldsm4(unsigned* r, unsigned addr) {
    asm volatile("ldmatrix.sync.aligned.m8n8.x4.shared.b16 {%0,%1,%2,%3},[%4];"
                 : "=r"(r[0]), "=r"(r[1]), "=r"(r[2]), "=r"(r[3]) : "r"(addr));
}
__device__ __forceinline__ void ldsm4t(unsigned* r, unsigned addr) {
    asm volatile("ldmatrix.sync.aligned.m8n8.x4.trans.shared.b16 {%0,%1,%2,%3},[%4];"
                 : "=r"(r[0]), "=r"(r[1]), "=r"(r[2]), "=r"(r[3]) : "r"(addr));
}

__device__ __forceinline__ void cpa16(unsigned dst, const void* src) {
    asm volatile("cp.async.cg.shared.global [%0],[%1],16;" :: "r"(dst), "l"(src));
}
__device__ __forceinline__ void cpcommit() { asm volatile("cp.async.commit_group;"); }
__device__ __forceinline__ void cpwait0()  { asm volatile("cp.async.wait_group 0;"); }
__device__ __forceinline__ void cpwait1()  { asm volatile("cp.async.wait_group 1;"); }

__device__ __forceinline__ unsigned sptr(const void* p) {
    return (unsigned)__cvta_generic_to_shared(p);
}

// output helpers (fp32 with bias / fp16 packed)
__device__ __forceinline__ void st2(float* C, size_t off, float a, float b, float b0, float b1) {
    *(float2*)(C + off) = make_float2(a + b0, b + b1);
}
__device__ __forceinline__ void st2(__half* C, size_t off, float a, float b, float, float) {
    *(unsigned*)(C + off) = ph2(a, b);
}

// ---------------------------------------------------------------------------
// fp32 -> fp16 conversion (8 elems / thread)
// ---------------------------------------------------------------------------
__global__ __launch_bounds__(256) void f2h(const float* __restrict__ s,
                                           __half* __restrict__ d, int n)
{
    int i = (blockIdx.x * blockDim.x + threadIdx.x) * 8;
    if (i >= n) return;
    float4 v0 = *(const float4*)(s + i);
    float4 v1 = *(const float4*)(s + i + 4);
    uint4 o = make_uint4(ph2(v0.x, v0.y), ph2(v0.z, v0.w),
                         ph2(v1.x, v1.y), ph2(v1.z, v1.w));
    *(uint4*)(d + i) = o;
}

// ---------------------------------------------------------------------------
// fp16 MMA GEMM: C[M,N] = A[M,K] @ B[K,N] (+bias). BK=32, 2-stage cp.async,
// ldmatrix fragments. 128 x BN tile, 256 threads (8 warps, 4m x 2n).
// Requires M%128==0, N%BN==0, K%32==0. BN in {128, 64}.
// Smem: As[128][56 halfs] (112B rows, conflict-free ldmatrix),
//       Bs[32][BN+8 halfs] (272/144B rows).
// ---------------------------------------------------------------------------
template<int BN, typename OutT>
__global__ __launch_bounds__(256) void hgemm16(
    const __half* __restrict__ A, const __half* __restrict__ B,
    const float* __restrict__ bias, OutT* __restrict__ C,
    int M, int N, int K)
{
    constexpr int NT = BN / 16;
    constexpr int ASTR = 112;                 // bytes per A smem row
    constexpr int BSTR = (BN == 128) ? 272 : 144;
    constexpr int ASTAGE = 128 * ASTR;        // 14336
    constexpr int BSTAGE = 32 * BSTR;

    __shared__ __align__(16) char smem[2 * ASTAGE + 2 * BSTAGE];
    const unsigned uA = sptr(smem);
    const unsigned uB = uA + 2 * ASTAGE;

    const int tid  = threadIdx.x;
    const int lane = tid & 31;
    const int w    = tid >> 5;
    const int g    = lane >> 2;
    const int tig  = lane & 3;
    const int wm   = (w & 3) * 32;
    const int wn   = (w >> 2) * (BN / 2);
    const int m0   = blockIdx.y * 128;
    const int n0   = blockIdx.x * BN;

    // fill mapping
    const int far = tid >> 1;                 // A row
    const int fac = (tid & 1) * 2;            // A 16B-chunk base (of 4)
    const int fbk = tid >> 3;                 // B k row
    const int fbc = (BN == 128) ? (tid & 7) * 2 : (tid & 7);

    const __half* Asrc = A + (size_t)(m0 + far) * K + fac * 8;
    const __half* Bsrc = B + (size_t)fbk * N + n0 + fbc * 8;
    const unsigned adst = uA + far * ASTR + fac * 16;
    const unsigned bdst = uB + fbk * BSTR + fbc * 16;

    float acc[2][NT][4];
#pragma unroll
    for (int mt = 0; mt < 2; ++mt)
#pragma unroll
        for (int nt = 0; nt < NT; ++nt)
#pragma unroll
            for (int i = 0; i < 4; ++i) acc[mt][nt][i] = 0.f;

    const int niters = K >> 5;

    // prefetch stage 0
    cpa16(adst, Asrc); cpa16(adst + 16, Asrc + 8);
    cpa16(bdst, Bsrc);
    if (BN == 128) cpa16(bdst + 16, Bsrc + 8);
    cpcommit();

    for (int it = 0; it < niters; ++it) {
        if (it + 1 < niters) {
            const int st = (it + 1) & 1;
            const __half* as = Asrc + (it + 1) * 32;
            const __half* bs = Bsrc + (size_t)(it + 1) * 32 * N;
            cpa16(adst + st * ASTAGE, as); cpa16(adst + st * ASTAGE + 16, as + 8);
            cpa16(bdst + st * BSTAGE, bs);
            if (BN == 128) cpa16(bdst + st * BSTAGE + 16, bs + 8);
            cpcommit();
            cpwait1();
        } else {
            cpwait0();
        }
        __syncthreads();

        const int st = it & 1;
        const unsigned aAb = uA + st * ASTAGE + (wm + (lane & 15)) * ASTR + ((lane >> 4) << 4);
        unsigned af[2][2][4];
#pragma unroll
        for (int kc = 0; kc < 2; ++kc)
#pragma unroll
            for (int mt = 0; mt < 2; ++mt)
                ldsm4(af[kc][mt], aAb + mt * 16 * ASTR + kc * 32);

        const unsigned aBb = uB + st * BSTAGE + (lane & 15) * BSTR
                           + (wn + ((lane >> 4) << 3)) * 2;
#pragma unroll
        for (int kc = 0; kc < 2; ++kc) {
#pragma unroll
            for (int np = 0; np < NT / 2; ++np) {
                unsigned bf[4];
                ldsm4t(bf, aBb + kc * 16 * BSTR + np * 32);
                mma16(acc[0][2 * np],     af[kc][0], bf[0], bf[1]);
                mma16(acc[1][2 * np],     af[kc][1], bf[0], bf[1]);
                mma16(acc[0][2 * np + 1], af[kc][0], bf[2], bf[3]);
                mma16(acc[1][2 * np + 1], af[kc][1], bf[2], bf[3]);
            }
        }
        __syncthreads();
    }

    // epilogue
#pragma unroll
    for (int mt = 0; mt < 2; ++mt) {
        const int r0 = m0 + wm + mt * 16 + g;
#pragma unroll
        for (int nt = 0; nt < NT; ++nt) {
            const int c0 = n0 + wn + nt * 8 + 2 * tig;
            float b0 = 0.f, b1 = 0.f;
            if (bias) { b0 = bias[c0]; b1 = bias[c0 + 1]; }
            st2(C, (size_t)r0 * N + c0,       acc[mt][nt][0], acc[mt][nt][1], b0, b1);
            st2(C, (size_t)(r0 + 8) * N + c0, acc[mt][nt][2], acc[mt][nt][3], b0, b1);
        }
    }
}

// ---------------------------------------------------------------------------
// LayerNorm over R=64 per row: fp32 in, fp16 out
// ---------------------------------------------------------------------------
__global__ __launch_bounds__(256) void ln_kernel(
    const float* __restrict__ ckv, __half* __restrict__ out,
    const float* __restrict__ g, const float* __restrict__ bpar)
{
    const int row  = blockIdx.x * 8 + (threadIdx.x >> 5);
    const int lane = threadIdx.x & 31;
    const float* ptr = ckv + (size_t)row * RR;
    float v0 = ptr[lane], v1 = ptr[lane + 32];
    float s = v0 + v1, sq = v0 * v0 + v1 * v1;
#pragma unroll
    for (int o = 16; o; o >>= 1) {
        s  += __shfl_xor_sync(0xffffffffu, s,  o);
        sq += __shfl_xor_sync(0xffffffffu, sq, o);
    }
    float mean = s * (1.f / RR);
    float var  = sq * (1.f / RR) - mean * mean;
    float inv  = rsqrtf(var + 1e-5f);
    __half* op = out + (size_t)row * RR;
    op[lane]      = __float2half((v0 - mean) * inv * g[lane]      + bpar[lane]);
    op[lane + 32] = __float2half((v1 - mean) * inv * g[lane + 32] + bpar[lane + 32]);
}

// ---------------------------------------------------------------------------
// RoPE (rotate-half) on fp16 array, in-place, optional extra scale.
// ---------------------------------------------------------------------------
__global__ __launch_bounds__(256) void rope_h(__half* __restrict__ ptr, int rowStride, float scale)
{
    int idx = blockIdx.x * blockDim.x + threadIdx.x;
    if (idx >= MROWS * HH * 32) return;
    int i   = idx & 31;
    int h   = (idx >> 5) % HH;
    int row = idx / (HH * 32);
    int t   = row & (TT - 1);

    float inv = exp2f(-(float)i * (13.287712379549449f / 32.f));
    float ang = (float)t * inv;
    float sn, cs;
    sincosf(ang, &sn, &cs);

    __half* base = ptr + (size_t)row * rowStride + h * DD;
    float x0 = __half2float(base[i]), x1 = __half2float(base[i + 32]);
    base[i]      = __float2half((x0 * cs - x1 * sn) * scale);
    base[i + 32] = __float2half((x1 * cs + x0 * sn) * scale);
}

// ---------------------------------------------------------------------------
// Causal flash attention: fp16 in (q pre-scaled by SCALE*log2e), fp16 out.
// grid=(T/128,H,B) reversed; 256 threads, 8 warps x 16 q-rows.
// Smem: Qp[128][72h], Ks[2][64][72h], Vs[2][64][72h] (144B rows, conflict-free).
// cp.async double-buffered KV; all fragments via ldmatrix.
// ---------------------------------------------------------------------------
#define KVBYTES (64 * 144)
#define QBYTES  (128 * 144)
#define ASMEM   (QBYTES + 4 * KVBYTES)   // 55296

__global__ __launch_bounds__(256, 2) void attn_f16(
    const __half* __restrict__ q, const __half* __restrict__ kv, __half* __restrict__ ao)
{
    extern __shared__ __align__(16) char sm[];
    const unsigned uQ = sptr(sm);
    const unsigned uK = uQ + QBYTES;
    const unsigned uV = uK + 2 * KVBYTES;

    const int tid  = threadIdx.x;
    const int lane = tid & 31;
    const int w    = tid >> 5;
    const int g    = lane >> 2;
    const int tig  = lane & 3;
    const int qi   = (gridDim.x - 1) - blockIdx.x;
    const int i0   = qi * 128;
    const int h    = blockIdx.y;
    const int b    = blockIdx.z;
    const int rb   = w * 16;
    const int row_min = i0 + rb;
    const int row_max = row_min + 15;

    // --- Q fill (plain 16B copies; warp-local rows) ---
    {
        const int r  = tid >> 1;
        const int hh = (tid & 1) * 32;
        const uint4* src = (const uint4*)(q + (size_t)(b * TT + i0 + r) * CC + h * DD + hh);
        char* dst = sm + r * 144 + hh * 2;
        uint4 v0 = src[0], v1 = src[1], v2 = src[2], v3 = src[3];
        *(uint4*)dst = v0; *(uint4*)(dst + 16) = v1;
        *(uint4*)(dst + 32) = v2; *(uint4*)(dst + 48) = v3;
    }
    __syncwarp();

    // Q fragments (4 k16 chunks over D=64)
    unsigned qa[4][4];
    {
        const unsigned aQ = uQ + (rb + (lane & 15)) * 144 + ((lane >> 4) << 4);
#pragma unroll
        for (int kc = 0; kc < 4; ++kc) ldsm4(qa[kc], aQ + kc * 32);
    }

    // KV prefetch mapping: 2x16B K + 2x16B V per thread per tile
    const int fr = tid >> 2;
    const int fc = (tid & 3) * 2;
    const size_t kvrow0 = (size_t)(b * TT) * KVW + h * DD + fc * 8;

    // prefetch tile 0
    {
        const __half* ks = kv + kvrow0 + (size_t)fr * KVW;
        const unsigned kd = uK + fr * 144 + fc * 16;
        cpa16(kd, ks); cpa16(kd + 16, ks + 8);
        const unsigned vd = uV + fr * 144 + fc * 16;
        cpa16(vd, ks + HH * DD); cpa16(vd + 16, ks + HH * DD + 8);
    }
    cpcommit();

    float mr0 = -INFINITY, mr1 = -INFINITY, l0 = 0.f, l1 = 0.f;
    float oacc[8][4];
#pragma unroll
    for (int nt = 0; nt < 8; ++nt)
#pragma unroll
        for (int i = 0; i < 4; ++i) oacc[nt][i] = 0.f;

    const int ntile = 2 * qi + 2;
    for (int jt = 0; jt < ntile; ++jt) {
        if (jt + 1 < ntile) {
            const int st = (jt + 1) & 1;
            const __half* ks = kv + kvrow0 + (size_t)((jt + 1) * 64 + fr) * KVW;
            const unsigned kd = uK + st * KVBYTES + fr * 144 + fc * 16;
            cpa16(kd, ks); cpa16(kd + 16, ks + 8);
            const unsigned vd = uV + st * KVBYTES + fr * 144 + fc * 16;
            cpa16(vd, ks + HH * DD); cpa16(vd + 16, ks + HH * DD + 8);
            cpcommit();
            cpwait1();
        } else {
            cpwait0();
        }
        __syncthreads();

        const int j0 = jt * 64;
        if (j0 <= row_max) {
            const int st = jt & 1;

            // --- S = Q K^T ---
            float sacc[8][4];
#pragma unroll
            for (int nt = 0; nt < 8; ++nt)
#pragma unroll
                for (int i = 0; i < 4; ++i) sacc[nt][i] = 0.f;

            const unsigned aK = uK + st * KVBYTES
                              + ((lane & 7) + ((lane & 16) >> 1)) * 144 + ((lane & 8) << 1);
#pragma unroll
            for (int kc = 0; kc < 4; ++kc) {
#pragma unroll
                for (int np = 0; np < 4; ++np) {
                    unsigned bf[4];
                    ldsm4(bf, aK + np * 16 * 144 + kc * 32);
                    mma16(sacc[2 * np],     qa[kc], bf[0], bf[1]);
                    mma16(sacc[2 * np + 1], qa[kc], bf[2], bf[3]);
                }
            }

            // --- causal mask (partial tile only) ---
            if (j0 + 63 > row_min) {
                const int r0g = row_min + g, r1g = r0g + 8;
#pragma unroll
                for (int nt = 0; nt < 8; ++nt) {
                    const int c = j0 + nt * 8 + 2 * tig;
                    if (c > r0g)     sacc[nt][0] = -INFINITY;
                    if (c + 1 > r0g) sacc[nt][1] = -INFINITY;
                    if (c > r1g)     sacc[nt][2] = -INFINITY;
                    if (c + 1 > r1g) sacc[nt][3] = -INFINITY;
                }
            }

            // --- online softmax (base 2) ---
            float tm0 = -INFINITY, tm1 = -INFINITY;
#pragma unroll
            for (int nt = 0; nt < 8; ++nt) {
                tm0 = fmaxf(tm0, fmaxf(sacc[nt][0], sacc[nt][1]));
                tm1 = fmaxf(tm1, fmaxf(sacc[nt][2], sacc[nt][3]));
            }
            tm0 = fmaxf(tm0, __shfl_xor_sync(0xffffffffu, tm0, 1));
            tm0 = fmaxf(tm0, __shfl_xor_sync(0xffffffffu, tm0, 2));
            tm1 = fmaxf(tm1, __shfl_xor_sync(0xffffffffu, tm1, 1));
            tm1 = fmaxf(tm1, __shfl_xor_sync(0xffffffffu, tm1, 2));

            const float mn0 = fmaxf(mr0, tm0), mn1 = fmaxf(mr1, tm1);
            const float al0 = exp2f(mr0 - mn0), al1 = exp2f(mr1 - mn1);
            float s0 = 0.f, s1 = 0.f;
#pragma unroll
            for (int nt = 0; nt < 8; ++nt) {
                sacc[nt][0] = exp2f(sacc[nt][0] - mn0);
                sacc[nt][1] = exp2f(sacc[nt][1] - mn0);
                sacc[nt][2] = exp2f(sacc[nt][2] - mn1);
                sacc[nt][3] = exp2f(sacc[nt][3] - mn1);
                s0 += sacc[nt][0] + sacc[nt][1];
                s1 += sacc[nt][2] + sacc[nt][3];
            }
            s0 += __shfl_xor_sync(0xffffffffu, s0, 1);
            s0 += __shfl_xor_sync(0xffffffffu, s0, 2);
            s1 += __shfl_xor_sync(0xffffffffu, s1, 1);
            s1 += __shfl_xor_sync(0xffffffffu, s1, 2);
            l0 = l0 * al0 + s0;
            l1 = l1 * al1 + s1;
            mr0 = mn0; mr1 = mn1;
#pragma unroll
            for (int nt = 0; nt < 8; ++nt) {
                oacc[nt][0] *= al0; oacc[nt][1] *= al0;
                oacc[nt][2] *= al1; oacc[nt][3] *= al1;
            }

            // --- pack P to fp16 (register-resident) ---
            unsigned pfr[4][4];
#pragma unroll
            for (int kk = 0; kk < 4; ++kk) {
                pfr[kk][0] = ph2(sacc[2 * kk][0],     sacc[2 * kk][1]);
                pfr[kk][1] = ph2(sacc[2 * kk][2],     sacc[2 * kk][3]);
                pfr[kk][2] = ph2(sacc[2 * kk + 1][0], sacc[2 * kk + 1][1]);
                pfr[kk][3] = ph2(sacc[2 * kk + 1][2], sacc[2 * kk + 1][3]);
            }

            // --- O += P V ---
            const unsigned aV = uV + st * KVBYTES + (lane & 15) * 144 + (lane & 16);
#pragma unroll
            for (int kc = 0; kc < 4; ++kc) {
#pragma unroll
                for (int np = 0; np < 4; ++np) {
                    unsigned bf[4];
                    ldsm4t(bf, aV + kc * 16 * 144 + np * 32);
                    mma16(oacc[2 * np],     pfr[kc], bf[0], bf[1]);
                    mma16(oacc[2 * np + 1], pfr[kc], bf[2], bf[3]);
                }
            }
        }
        __syncthreads();
    }

    // --- finalize (fp16 out) ---
    const float inv0 = 1.f / l0, inv1 = 1.f / l1;
    __half* dst0 = ao + (size_t)(b * TT + i0 + rb + g) * CC + h * DD;
    __half* dst1 = dst0 + (size_t)8 * CC;
#pragma unroll
    for (int nt = 0; nt < 8; ++nt) {
        const int c = nt * 8 + 2 * tig;
        *(unsigned*)(dst0 + c) = ph2(oacc[nt][0] * inv0, oacc[nt][1] * inv0);
        *(unsigned*)(dst1 + c) = ph2(oacc[nt][2] * inv1, oacc[nt][3] * inv1);
    }
}

// ---------------------------------------------------------------------------
// Launch
// ---------------------------------------------------------------------------
extern "C" void kernel_launch(void* const* d_in, const int* in_sizes, int n_in,
                              void* d_out, int out_size)
{
    const float* x     = (const float*)d_in[0];
    const float* Wq    = (const float*)d_in[1];
    const float* Wdown = (const float*)d_in[2];
    const float* ln_g  = (const float*)d_in[3];
    const float* ln_b  = (const float*)d_in[4];
    const float* Wup   = (const float*)d_in[5];
    const float* Wo    = (const float*)d_in[6];
    const float* bo    = (const float*)d_in[7];
    float* out = (float*)d_out;

    void *pxh, *pq, *pckv, *pckvh, *pkv, *pao, *pwq, *pwdn, *pwup, *pwo;
    cudaGetSymbolAddress(&pxh,  g_xh);
    cudaGetSymbolAddress(&pq,   g_q16);
    cudaGetSymbolAddress(&pckv, g_ckv);
    cudaGetSymbolAddress(&pckvh,g_ckvh);
    cudaGetSymbolAddress(&pkv,  g_kv16);
    cudaGetSymbolAddress(&pao,  g_ao16);
    cudaGetSymbolAddress(&pwq,  g_wq);
    cudaGetSymbolAddress(&pwdn, g_wdn);
    cudaGetSymbolAddress(&pwup, g_wup);
    cudaGetSymbolAddress(&pwo,  g_wo);
    __half* xh   = (__half*)pxh;
    __half* q16  = (__half*)pq;
    float*  ckv  = (float*)pckv;
    __half* ckvh = (__half*)pckvh;
    __half* kv16 = (__half*)pkv;
    __half* ao16 = (__half*)pao;
    __half* wq   = (__half*)pwq;
    __half* wdn  = (__half*)pwdn;
    __half* wup  = (__half*)pwup;
    __half* wo   = (__half*)pwo;

    cudaFuncSetAttribute(attn_f16, cudaFuncAttributeMaxDynamicSharedMemorySize, ASMEM);

    // 0) conversions to fp16
    f2h<<<(MROWS * CC) / (256 * 8), 256>>>(x, xh, MROWS * CC);
    f2h<<<(CC * HH * DD) / (256 * 8), 256>>>(Wq, wq, CC * HH * DD);
    f2h<<<(CC * RR) / (256 * 8), 256>>>(Wdown, wdn, CC * RR);
    f2h<<<(RR * KVW) / (256 * 8), 256>>>(Wup, wup, RR * KVW);
    f2h<<<(HH * DD * CC) / (256 * 8), 256>>>(Wo, wo, HH * DD * CC);

    // 1) q = x @ Wq  (fp16 out)
    hgemm16<128, __half><<<dim3(CC / 128, MROWS / 128), 256>>>(
        xh, wq, nullptr, q16, MROWS, CC, CC);
    // 2) ckv = x @ Wdown  (fp32 out)
    hgemm16<64, float><<<dim3(RR / 64, MROWS / 128), 256>>>(
        xh, wdn, nullptr, ckv, MROWS, RR, CC);
    // 3) layernorm -> fp16
    ln_kernel<<<MROWS / 8, 256>>>(ckv, ckvh, ln_g, ln_b);
    // 4) kv = ckv @ Wup  (fp16 out)
    hgemm16<128, __half><<<dim3(KVW / 128, MROWS / 128), 256>>>(
        ckvh, wup, nullptr, kv16, MROWS, KVW, RR);
    // 5) RoPE (q gets SCALE*log2e folded in)
    {
        int total = MROWS * HH * 32;
        int blocks = (total + 255) / 256;
        rope_h<<<blocks, 256>>>(q16, CC, SCALE * LOG2E);
        rope_h<<<blocks, 256>>>(kv16, KVW, 1.0f);
    }
    // 6) attention
    attn_f16<<<dim3(TT / 128, HH, BB), 256, ASMEM>>>(q16, kv16, ao16);
    // 7) out = ao @ Wo + bo  (fp32 out)
    hgemm16<128, float><<<dim3(CC / 128, MROWS / 128), 256>>>(
        ao16, wo, bo, out, MROWS, CC, CC);
}

// round 7
// speedup vs baseline: 16.1438x; 1.0810x over previous
#include <cuda_runtime.h>
#include <cuda_fp16.h>
#include <math.h>
#include <float.h>

// ---------------------------------------------------------------------------
// MLA forward, fp16 dataflow, fused epilogues (RoPE / LayerNorm / bias).
//   B=4, T=2048, C=768, H=12, D=64, R=64
// ---------------------------------------------------------------------------

#define BB 4
#define TT 2048
#define CC 768
#define HH 12
#define DD 64
#define RR 64
#define MROWS (BB * TT)            // 8192
#define KVW (2 * HH * DD)          // 1536
#define SCALE 0.125f
#define LOG2E 1.4426950408889634f

// Scratch (device globals)
__device__ __half g_xh  [MROWS * CC];
__device__ __half g_q16 [MROWS * CC];
__device__ __half g_ckvh[MROWS * RR];
__device__ __half g_kv16[MROWS * KVW];
__device__ __half g_ao16[MROWS * CC];
__device__ __half g_wq  [CC * HH * DD];
__device__ __half g_wdn [CC * RR];
__device__ __half g_wup [RR * KVW];
__device__ __half g_wo  [HH * DD * CC];
__device__ float2 g_rt  [TT * 32];       // rope cos/sin table

// ---------------------------------------------------------------------------
// helpers
// ---------------------------------------------------------------------------
__device__ __forceinline__ unsigned ph2(float lo, float hi) {
    __half2 h = __floats2half2_rn(lo, hi);
    return *(unsigned*)&h;
}

__device__ __forceinline__ void mma16(float* c, const unsigned* a, unsigned b0, unsigned b1) {
    asm volatile(
        "mma.sync.aligned.m16n8k16.row.col.f32.f16.f16.f32 "
        "{%0,%1,%2,%3},{%4,%5,%6,%7},{%8,%9},{%0,%1,%2,%3};"
        : "+f"(c[0]), "+f"(c[1]), "+f"(c[2]), "+f"(c[3])
        : "r"(a[0]), "r"(a[1]), "r"(a[2]), "r"(a[3]), "r"(b0), "r"(b1));
}

__device__ __forceinline__ void ldsm4(unsigned* r, unsigned addr) {
    asm volatile("ldmatrix.sync.aligned.m8n8.x4.shared.b16 {%0,%1,%2,%3},[%4];"
                 : "=r"(r[0]), "=r"(r[1]), "=r"(r[2]), "=r"(r[3]) : "r"(addr));
}
__device__ __forceinline__ void ldsm4t(unsigned* r, unsigned addr) {
    asm volatile("ldmatrix.sync.aligned.m8n8.x4.trans.shared.b16 {%0,%1,%2,%3},[%4];"
                 : "=r"(r[0]), "=r"(r[1]), "=r"(r[2]), "=r"(r[3]) : "r"(addr));
}

__device__ __forceinline__ void cpa16(unsigned dst, const void* src) {
    asm volatile("cp.async.cg.shared.global [%0],[%1],16;" :: "r"(dst), "l"(src));
}
__device__ __forceinline__ void cpcommit() { asm volatile("cp.async.commit_group;"); }
__device__ __forceinline__ void cpwait0()  { asm volatile("cp.async.wait_group 0;"); }
__device__ __forceinline__ void cpwait1()  { asm volatile("cp.async.wait_group 1;"); }

__device__ __forceinline__ unsigned sptr(const void* p) {
    return (unsigned)__cvta_generic_to_shared(p);
}

// ---------------------------------------------------------------------------
// rope table:  g_rt[t*32+d] = (cos, sin) of t * 10000^(-d/32)
// ---------------------------------------------------------------------------
__global__ __launch_bounds__(256) void rope_tab_k(float2* tab)
{
    int i = blockIdx.x * 256 + threadIdx.x;       // 65536 total
    int d = i & 31, t = i >> 5;
    float inv = exp2f(-(float)d * (13.287712379549449f / 32.f));
    float sn, cs;
    sincosf((float)t * inv, &sn, &cs);
    tab[i] = make_float2(cs, sn);
}

// ---------------------------------------------------------------------------
// merged fp32 -> fp16 conversion of x + 4 weights (one launch)
// ---------------------------------------------------------------------------
__device__ __forceinline__ void conv8(const float* s, __half* d) {
    float4 v0 = *(const float4*)s;
    float4 v1 = *(const float4*)(s + 4);
    uint4 o = make_uint4(ph2(v0.x, v0.y), ph2(v0.z, v0.w),
                         ph2(v1.x, v1.y), ph2(v1.z, v1.w));
    *(uint4*)d = o;
}

#define C0 (MROWS * CC / 8)                         // 786432
#define C1 (C0 + CC * HH * DD / 8)                  // 860160
#define C2 (C1 + CC * RR / 8)                       // 866304
#define C3 (C2 + RR * KVW / 8)                      // 878592
#define C4 (C3 + HH * DD * CC / 8)                  // 952320

__global__ __launch_bounds__(256) void f2h_all(
    const float* __restrict__ x,  const float* __restrict__ wq,
    const float* __restrict__ wdn,const float* __restrict__ wup,
    const float* __restrict__ wo,
    __half* __restrict__ xh, __half* __restrict__ hq, __half* __restrict__ hdn,
    __half* __restrict__ hup, __half* __restrict__ ho)
{
    int i = blockIdx.x * 256 + threadIdx.x;
    if      (i < C0) { int k = i * 8;            conv8(x + k,   xh + k); }
    else if (i < C1) { int k = (i - C0) * 8;     conv8(wq + k,  hq + k); }
    else if (i < C2) { int k = (i - C1) * 8;     conv8(wdn + k, hdn + k); }
    else if (i < C3) { int k = (i - C2) * 8;     conv8(wup + k, hup + k); }
    else             { int k = (i - C3) * 8;     conv8(wo + k,  ho + k); }
}

// ---------------------------------------------------------------------------
// fp16 MMA GEMM with fused epilogue.
//   EPI 1: fp32 out + bias                 (Wo)
//   EPI 2: fp16 out, RoPE on cols < ropeLimit, then *ropeScale   (Wq, Wup)
//   EPI 3: fp16 out, row LayerNorm over N=64                      (Wdown)
// 128 x BN tile, BK=32, 2-stage cp.async, ldmatrix. 256 threads.
// ---------------------------------------------------------------------------
template<int BN, int EPI, typename OutT>
__global__ __launch_bounds__(256) void hgemm16(
    const __half* __restrict__ A, const __half* __restrict__ B,
    OutT* __restrict__ C, int M, int N, int K,
    const float* __restrict__ bias,
    const float2* __restrict__ rt, float ropeScale, int ropeLimit,
    const float* __restrict__ lng, const float* __restrict__ lnb)
{
    constexpr int NT = BN / 16;
    constexpr int ASTR = 112;
    constexpr int BSTR = (BN == 128) ? 272 : 144;
    constexpr int ASTAGE = 128 * ASTR;
    constexpr int BSTAGE = 32 * BSTR;

    __shared__ __align__(16) char smem[2 * ASTAGE + 2 * BSTAGE];
    const unsigned uA = sptr(smem);
    const unsigned uB = uA + 2 * ASTAGE;

    const int tid  = threadIdx.x;
    const int lane = tid & 31;
    const int w    = tid >> 5;
    const int g    = lane >> 2;
    const int tig  = lane & 3;
    const int wm   = (w & 3) * 32;
    const int wn   = (w >> 2) * (BN / 2);
    const int m0   = blockIdx.y * 128;
    const int n0   = blockIdx.x * BN;

    const int far = tid >> 1;
    const int fac = (tid & 1) * 2;
    const int fbk = tid >> 3;
    const int fbc = (BN == 128) ? (tid & 7) * 2 : (tid & 7);

    const __half* Asrc = A + (size_t)(m0 + far) * K + fac * 8;
    const __half* Bsrc = B + (size_t)fbk * N + n0 + fbc * 8;
    const unsigned adst = uA + far * ASTR + fac * 16;
    const unsigned bdst = uB + fbk * BSTR + fbc * 16;

    float acc[2][NT][4];
#pragma unroll
    for (int mt = 0; mt < 2; ++mt)
#pragma unroll
        for (int nt = 0; nt < NT; ++nt)
#pragma unroll
            for (int i = 0; i < 4; ++i) acc[mt][nt][i] = 0.f;

    const int niters = K >> 5;

    cpa16(adst, Asrc); cpa16(adst + 16, Asrc + 8);
    cpa16(bdst, Bsrc);
    if (BN == 128) cpa16(bdst + 16, Bsrc + 8);
    cpcommit();

    for (int it = 0; it < niters; ++it) {
        if (it + 1 < niters) {
            const int st = (it + 1) & 1;
            const __half* as = Asrc + (it + 1) * 32;
            const __half* bs = Bsrc + (size_t)(it + 1) * 32 * N;
            cpa16(adst + st * ASTAGE, as); cpa16(adst + st * ASTAGE + 16, as + 8);
            cpa16(bdst + st * BSTAGE, bs);
            if (BN == 128) cpa16(bdst + st * BSTAGE + 16, bs + 8);
            cpcommit();
            cpwait1();
        } else {
            cpwait0();
        }
        __syncthreads();

        const int st = it & 1;
        const unsigned aAb = uA + st * ASTAGE + (wm + (lane & 15)) * ASTR + ((lane >> 4) << 4);
        unsigned af[2][2][4];
#pragma unroll
        for (int kc = 0; kc < 2; ++kc)
#pragma unroll
            for (int mt = 0; mt < 2; ++mt)
                ldsm4(af[kc][mt], aAb + mt * 16 * ASTR + kc * 32);

        const unsigned aBb = uB + st * BSTAGE + (lane & 15) * BSTR
                           + (wn + ((lane >> 4) << 3)) * 2;
#pragma unroll
        for (int kc = 0; kc < 2; ++kc) {
#pragma unroll
            for (int np = 0; np < NT / 2; ++np) {
                unsigned bf[4];
                ldsm4t(bf, aBb + kc * 16 * BSTR + np * 32);
                mma16(acc[0][2 * np],     af[kc][0], bf[0], bf[1]);
                mma16(acc[1][2 * np],     af[kc][1], bf[0], bf[1]);
                mma16(acc[0][2 * np + 1], af[kc][0], bf[2], bf[3]);
                mma16(acc[1][2 * np + 1], af[kc][1], bf[2], bf[3]);
            }
        }
        __syncthreads();
    }

    // ------------------------- epilogues -------------------------
    if constexpr (EPI == 1) {
        // fp32 + bias
#pragma unroll
        for (int mt = 0; mt < 2; ++mt) {
            const int r0 = m0 + wm + mt * 16 + g;
#pragma unroll
            for (int nt = 0; nt < NT; ++nt) {
                const int c0 = n0 + wn + nt * 8 + 2 * tig;
                const float b0 = bias[c0], b1 = bias[c0 + 1];
                *(float2*)((float*)C + (size_t)r0 * N + c0) =
                    make_float2(acc[mt][nt][0] + b0, acc[mt][nt][1] + b1);
                *(float2*)((float*)C + (size_t)(r0 + 8) * N + c0) =
                    make_float2(acc[mt][nt][2] + b0, acc[mt][nt][3] + b1);
            }
        }
    } else if constexpr (EPI == 2) {
        // fp16 out, rope on the 64-wide head this warp owns (uniform branch)
        const bool doRope = (n0 + wn) < ropeLimit;
        __half* Ch = (__half*)C;
#pragma unroll
        for (int mt = 0; mt < 2; ++mt) {
            const int r0 = m0 + wm + mt * 16 + g;
            const int t0 = r0 & (TT - 1);
#pragma unroll
            for (int ntp = 0; ntp < 4; ++ntp) {
                const int clo = n0 + wn + ntp * 8 + 2 * tig;
                float lo0[2], hi0[2], lo1[2], hi1[2];
                if (doRope) {
#pragma unroll
                    for (int j = 0; j < 2; ++j) {
                        const int d = ntp * 8 + 2 * tig + j;   // 0..31
                        const float2 cs0 = rt[t0 * 32 + d];
                        const float2 cs1 = rt[(t0 + 8) * 32 + d];
                        const float xl0 = acc[mt][ntp][j],     xh0 = acc[mt][ntp + 4][j];
                        const float xl1 = acc[mt][ntp][j + 2], xh1 = acc[mt][ntp + 4][j + 2];
                        lo0[j] = xl0 * cs0.x - xh0 * cs0.y;
                        hi0[j] = xh0 * cs0.x + xl0 * cs0.y;
                        lo1[j] = xl1 * cs1.x - xh1 * cs1.y;
                        hi1[j] = xh1 * cs1.x + xl1 * cs1.y;
                    }
                } else {
#pragma unroll
                    for (int j = 0; j < 2; ++j) {
                        lo0[j] = acc[mt][ntp][j];     hi0[j] = acc[mt][ntp + 4][j];
                        lo1[j] = acc[mt][ntp][j + 2]; hi1[j] = acc[mt][ntp + 4][j + 2];
                    }
                }
                const float s = ropeScale;
                *(unsigned*)(Ch + (size_t)r0 * N + clo) =
                    ph2(lo0[0] * s, lo0[1] * s);
                *(unsigned*)(Ch + (size_t)r0 * N + clo + 32) =
                    ph2(hi0[0] * s, hi0[1] * s);
                *(unsigned*)(Ch + (size_t)(r0 + 8) * N + clo) =
                    ph2(lo1[0] * s, lo1[1] * s);
                *(unsigned*)(Ch + (size_t)(r0 + 8) * N + clo + 32) =
                    ph2(hi1[0] * s, hi1[1] * s);
            }
        }
    } else if constexpr (EPI == 3) {
        // row layernorm over N=64 (BN==64), fp16 out
        float2* red = (float2*)smem;   // [2][128], overlay after main loop
        float rs[2][2], rq[2][2];
#pragma unroll
        for (int mt = 0; mt < 2; ++mt)
#pragma unroll
            for (int hh = 0; hh < 2; ++hh) {
                float s = 0.f, sq = 0.f;
#pragma unroll
                for (int nt = 0; nt < NT; ++nt)
#pragma unroll
                    for (int j = 0; j < 2; ++j) {
                        float v = acc[mt][nt][2 * hh + j];
                        s += v; sq += v * v;
                    }
                s  += __shfl_xor_sync(0xffffffffu, s, 1);
                s  += __shfl_xor_sync(0xffffffffu, s, 2);
                sq += __shfl_xor_sync(0xffffffffu, sq, 1);
                sq += __shfl_xor_sync(0xffffffffu, sq, 2);
                rs[mt][hh] = s; rq[mt][hh] = sq;
            }
        if (tig == 0) {
#pragma unroll
            for (int mt = 0; mt < 2; ++mt)
#pragma unroll
                for (int hh = 0; hh < 2; ++hh) {
                    const int rl = wm + mt * 16 + g + hh * 8;
                    red[(w >> 2) * 128 + rl] = make_float2(rs[mt][hh], rq[mt][hh]);
                }
        }
        __syncthreads();
        __half* Ch = (__half*)C;
#pragma unroll
        for (int mt = 0; mt < 2; ++mt)
#pragma unroll
            for (int hh = 0; hh < 2; ++hh) {
                const int rl = wm + mt * 16 + g + hh * 8;
                const float2 a = red[rl], bb = red[128 + rl];
                const float mean = (a.x + bb.x) * (1.f / 64.f);
                const float var  = (a.y + bb.y) * (1.f / 64.f) - mean * mean;
                const float inv  = rsqrtf(var + 1e-5f);
                const int r0 = m0 + rl;
#pragma unroll
                for (int nt = 0; nt < NT; ++nt) {
                    const int c = wn + nt * 8 + 2 * tig;
                    const float v0 = (acc[mt][nt][2 * hh]     - mean) * inv * lng[c]     + lnb[c];
                    const float v1 = (acc[mt][nt][2 * hh + 1] - mean) * inv * lng[c + 1] + lnb[c + 1];
                    *(unsigned*)(Ch + (size_t)r0 * N + c) = ph2(v0, v1);
                }
            }
    }
}

// ---------------------------------------------------------------------------
// Causal flash attention: fp16 in (q pre-scaled by SCALE*log2e), fp16 out.
// grid=(T/128,H,B) reversed; 256 threads, 8 warps x 16 q-rows.
// ---------------------------------------------------------------------------
#define KVBYTES (64 * 144)
#define QBYTES  (128 * 144)
#define ASMEM   (QBYTES + 4 * KVBYTES)   // 55296

__global__ __launch_bounds__(256, 2) void attn_f16(
    const __half* __restrict__ q, const __half* __restrict__ kv, __half* __restrict__ ao)
{
    extern __shared__ __align__(16) char sm[];
    const unsigned uQ = sptr(sm);
    const unsigned uK = uQ + QBYTES;
    const unsigned uV = uK + 2 * KVBYTES;

    const int tid  = threadIdx.x;
    const int lane = tid & 31;
    const int w    = tid >> 5;
    const int g    = lane >> 2;
    const int tig  = lane & 3;
    const int qi   = (gridDim.x - 1) - blockIdx.x;
    const int i0   = qi * 128;
    const int h    = blockIdx.y;
    const int b    = blockIdx.z;
    const int rb   = w * 16;
    const int row_min = i0 + rb;
    const int row_max = row_min + 15;

    // Q fill
    {
        const int r  = tid >> 1;
        const int hh = (tid & 1) * 32;
        const uint4* src = (const uint4*)(q + (size_t)(b * TT + i0 + r) * CC + h * DD + hh);
        char* dst = sm + r * 144 + hh * 2;
        uint4 v0 = src[0], v1 = src[1], v2 = src[2], v3 = src[3];
        *(uint4*)dst = v0; *(uint4*)(dst + 16) = v1;
        *(uint4*)(dst + 32) = v2; *(uint4*)(dst + 48) = v3;
    }
    __syncwarp();

    unsigned qa[4][4];
    {
        const unsigned aQ = uQ + (rb + (lane & 15)) * 144 + ((lane >> 4) << 4);
#pragma unroll
        for (int kc = 0; kc < 4; ++kc) ldsm4(qa[kc], aQ + kc * 32);
    }

    const int fr = tid >> 2;
    const int fc = (tid & 3) * 2;
    const size_t kvrow0 = (size_t)(b * TT) * KVW + h * DD + fc * 8;

    {
        const __half* ks = kv + kvrow0 + (size_t)fr * KVW;
        const unsigned kd = uK + fr * 144 + fc * 16;
        cpa16(kd, ks); cpa16(kd + 16, ks + 8);
        const unsigned vd = uV + fr * 144 + fc * 16;
        cpa16(vd, ks + HH * DD); cpa16(vd + 16, ks + HH * DD + 8);
    }
    cpcommit();

    float mr0 = -INFINITY, mr1 = -INFINITY, l0 = 0.f, l1 = 0.f;
    float oacc[8][4];
#pragma unroll
    for (int nt = 0; nt < 8; ++nt)
#pragma unroll
        for (int i = 0; i < 4; ++i) oacc[nt][i] = 0.f;

    const int ntile = 2 * qi + 2;
    for (int jt = 0; jt < ntile; ++jt) {
        if (jt + 1 < ntile) {
            const int st = (jt + 1) & 1;
            const __half* ks = kv + kvrow0 + (size_t)((jt + 1) * 64 + fr) * KVW;
            const unsigned kd = uK + st * KVBYTES + fr * 144 + fc * 16;
            cpa16(kd, ks); cpa16(kd + 16, ks + 8);
            const unsigned vd = uV + st * KVBYTES + fr * 144 + fc * 16;
            cpa16(vd, ks + HH * DD); cpa16(vd + 16, ks + HH * DD + 8);
            cpcommit();
            cpwait1();
        } else {
            cpwait0();
        }
        __syncthreads();

        const int j0 = jt * 64;
        if (j0 <= row_max) {
            const int st = jt & 1;

            float sacc[8][4];
#pragma unroll
            for (int nt = 0; nt < 8; ++nt)
#pragma unroll
                for (int i = 0; i < 4; ++i) sacc[nt][i] = 0.f;

            const unsigned aK = uK + st * KVBYTES
                              + ((lane & 7) + ((lane & 16) >> 1)) * 144 + ((lane & 8) << 1);
#pragma unroll
            for (int kc = 0; kc < 4; ++kc) {
#pragma unroll
                for (int np = 0; np < 4; ++np) {
                    unsigned bf[4];
                    ldsm4(bf, aK + np * 16 * 144 + kc * 32);
                    mma16(sacc[2 * np],     qa[kc], bf[0], bf[1]);
                    mma16(sacc[2 * np + 1], qa[kc], bf[2], bf[3]);
                }
            }

            if (j0 + 63 > row_min) {
                const int r0g = row_min + g, r1g = r0g + 8;
#pragma unroll
                for (int nt = 0; nt < 8; ++nt) {
                    const int c = j0 + nt * 8 + 2 * tig;
                    if (c > r0g)     sacc[nt][0] = -INFINITY;
                    if (c + 1 > r0g) sacc[nt][1] = -INFINITY;
                    if (c > r1g)     sacc[nt][2] = -INFINITY;
                    if (c + 1 > r1g) sacc[nt][3] = -INFINITY;
                }
            }

            float tm0 = -INFINITY, tm1 = -INFINITY;
#pragma unroll
            for (int nt = 0; nt < 8; ++nt) {
                tm0 = fmaxf(tm0, fmaxf(sacc[nt][0], sacc[nt][1]));
                tm1 = fmaxf(tm1, fmaxf(sacc[nt][2], sacc[nt][3]));
            }
            tm0 = fmaxf(tm0, __shfl_xor_sync(0xffffffffu, tm0, 1));
            tm0 = fmaxf(tm0, __shfl_xor_sync(0xffffffffu, tm0, 2));
            tm1 = fmaxf(tm1, __shfl_xor_sync(0xffffffffu, tm1, 1));
            tm1 = fmaxf(tm1, __shfl_xor_sync(0xffffffffu, tm1, 2));

            const float mn0 = fmaxf(mr0, tm0), mn1 = fmaxf(mr1, tm1);
            const float al0 = exp2f(mr0 - mn0), al1 = exp2f(mr1 - mn1);
            float s0 = 0.f, s1 = 0.f;
#pragma unroll
            for (int nt = 0; nt < 8; ++nt) {
                sacc[nt][0] = exp2f(sacc[nt][0] - mn0);
                sacc[nt][1] = exp2f(sacc[nt][1] - mn0);
                sacc[nt][2] = exp2f(sacc[nt][2] - mn1);
                sacc[nt][3] = exp2f(sacc[nt][3] - mn1);
                s0 += sacc[nt][0] + sacc[nt][1];
                s1 += sacc[nt][2] + sacc[nt][3];
            }
            s0 += __shfl_xor_sync(0xffffffffu, s0, 1);
            s0 += __shfl_xor_sync(0xffffffffu, s0, 2);
            s1 += __shfl_xor_sync(0xffffffffu, s1, 1);
            s1 += __shfl_xor_sync(0xffffffffu, s1, 2);
            l0 = l0 * al0 + s0;
            l1 = l1 * al1 + s1;
            mr0 = mn0; mr1 = mn1;
#pragma unroll
            for (int nt = 0; nt < 8; ++nt) {
                oacc[nt][0] *= al0; oacc[nt][1] *= al0;
                oacc[nt][2] *= al1; oacc[nt][3] *= al1;
            }

            unsigned pfr[4][4];
#pragma unroll
            for (int kk = 0; kk < 4; ++kk) {
                pfr[kk][0] = ph2(sacc[2 * kk][0],     sacc[2 * kk][1]);
                pfr[kk][1] = ph2(sacc[2 * kk][2],     sacc[2 * kk][3]);
                pfr[kk][2] = ph2(sacc[2 * kk + 1][0], sacc[2 * kk + 1][1]);
                pfr[kk][3] = ph2(sacc[2 * kk + 1][2], sacc[2 * kk + 1][3]);
            }

            const unsigned aV = uV + st * KVBYTES + (lane & 15) * 144 + (lane & 16);
#pragma unroll
            for (int kc = 0; kc < 4; ++kc) {
#pragma unroll
                for (int np = 0; np < 4; ++np) {
                    unsigned bf[4];
                    ldsm4t(bf, aV + kc * 16 * 144 + np * 32);
                    mma16(oacc[2 * np],     pfr[kc], bf[0], bf[1]);
                    mma16(oacc[2 * np + 1], pfr[kc], bf[2], bf[3]);
                }
            }
        }
        __syncthreads();
    }

    const float inv0 = 1.f / l0, inv1 = 1.f / l1;
    __half* dst0 = ao + (size_t)(b * TT + i0 + rb + g) * CC + h * DD;
    __half* dst1 = dst0 + (size_t)8 * CC;
#pragma unroll
    for (int nt = 0; nt < 8; ++nt) {
        const int c = nt * 8 + 2 * tig;
        *(unsigned*)(dst0 + c) = ph2(oacc[nt][0] * inv0, oacc[nt][1] * inv0);
        *(unsigned*)(dst1 + c) = ph2(oacc[nt][2] * inv1, oacc[nt][3] * inv1);
    }
}

// ---------------------------------------------------------------------------
// Launch
// ---------------------------------------------------------------------------
extern "C" void kernel_launch(void* const* d_in, const int* in_sizes, int n_in,
                              void* d_out, int out_size)
{
    const float* x     = (const float*)d_in[0];
    const float* Wq    = (const float*)d_in[1];
    const float* Wdown = (const float*)d_in[2];
    const float* ln_g  = (const float*)d_in[3];
    const float* ln_b  = (const float*)d_in[4];
    const float* Wup   = (const float*)d_in[5];
    const float* Wo    = (const float*)d_in[6];
    const float* bo    = (const float*)d_in[7];
    float* out = (float*)d_out;

    void *pxh, *pq, *pckvh, *pkv, *pao, *pwq, *pwdn, *pwup, *pwo, *prt;
    cudaGetSymbolAddress(&pxh,  g_xh);
    cudaGetSymbolAddress(&pq,   g_q16);
    cudaGetSymbolAddress(&pckvh,g_ckvh);
    cudaGetSymbolAddress(&pkv,  g_kv16);
    cudaGetSymbolAddress(&pao,  g_ao16);
    cudaGetSymbolAddress(&pwq,  g_wq);
    cudaGetSymbolAddress(&pwdn, g_wdn);
    cudaGetSymbolAddress(&pwup, g_wup);
    cudaGetSymbolAddress(&pwo,  g_wo);
    cudaGetSymbolAddress(&prt,  g_rt);
    __half* xh   = (__half*)pxh;
    __half* q16  = (__half*)pq;
    __half* ckvh = (__half*)pckvh;
    __half* kv16 = (__half*)pkv;
    __half* ao16 = (__half*)pao;
    __half* wq   = (__half*)pwq;
    __half* wdn  = (__half*)pwdn;
    __half* wup  = (__half*)pwup;
    __half* wo   = (__half*)pwo;
    float2* rt   = (float2*)prt;

    cudaFuncSetAttribute(attn_f16, cudaFuncAttributeMaxDynamicSharedMemorySize, ASMEM);

    // 0) rope table + merged conversions
    rope_tab_k<<<TT * 32 / 256, 256>>>(rt);
    f2h_all<<<C4 / 256, 256>>>(x, Wq, Wdown, Wup, Wo, xh, wq, wdn, wup, wo);

    // 1) q = rope(x @ Wq) * SCALE*log2e        (fp16)
    hgemm16<128, 2, __half><<<dim3(CC / 128, MROWS / 128), 256>>>(
        xh, wq, q16, MROWS, CC, CC, nullptr, rt, SCALE * LOG2E, CC, nullptr, nullptr);
    // 2) ckv = layernorm(x @ Wdown)            (fp16)
    hgemm16<64, 3, __half><<<dim3(RR / 64, MROWS / 128), 256>>>(
        xh, wdn, ckvh, MROWS, RR, CC, nullptr, nullptr, 0.f, 0, ln_g, ln_b);
    // 3) kv = ckv @ Wup, rope on K half        (fp16)
    hgemm16<128, 2, __half><<<dim3(KVW / 128, MROWS / 128), 256>>>(
        ckvh, wup, kv16, MROWS, KVW, RR, nullptr, rt, 1.0f, HH * DD, nullptr, nullptr);
    // 4) attention
    attn_f16<<<dim3(TT / 128, HH, BB), 256, ASMEM>>>(q16, kv16, ao16);
    // 5) out = ao @ Wo + bo                    (fp32)
    hgemm16<128, 1, float><<<dim3(CC / 128, MROWS / 128), 256>>>(
        ao16, wo, out, MROWS, CC, CC, bo, nullptr, 0.f, 0, nullptr, nullptr);
}

// round 8
// speedup vs baseline: 17.1858x; 1.0645x over previous
#include <cuda_runtime.h>
#include <cuda_fp16.h>
#include <math.h>
#include <float.h>

// ---------------------------------------------------------------------------
// MLA forward, fp16 dataflow, fused epilogues, MMA-computed softmax sums.
//   B=4, T=2048, C=768, H=12, D=64, R=64
// ---------------------------------------------------------------------------

#define BB 4
#define TT 2048
#define CC 768
#define HH 12
#define DD 64
#define RR 64
#define MROWS (BB * TT)            // 8192
#define KVW (2 * HH * DD)          // 1536
#define SCALE 0.125f
#define LOG2E 1.4426950408889634f

// Scratch (device globals)
__device__ __half g_xh  [MROWS * CC];
__device__ __half g_q16 [MROWS * CC];
__device__ __half g_ckvh[MROWS * RR];
__device__ __half g_kv16[MROWS * KVW];
__device__ __half g_ao16[MROWS * CC];
__device__ __half g_wq  [CC * HH * DD];
__device__ __half g_wdn [CC * RR];
__device__ __half g_wup [RR * KVW];
__device__ __half g_wo  [HH * DD * CC];
__device__ float2 g_rt  [TT * 32];       // rope cos/sin table

// ---------------------------------------------------------------------------
// helpers
// ---------------------------------------------------------------------------
__device__ __forceinline__ unsigned ph2(float lo, float hi) {
    __half2 h = __floats2half2_rn(lo, hi);
    return *(unsigned*)&h;
}

__device__ __forceinline__ unsigned ex2h2(unsigned x) {
    unsigned r;
    asm("ex2.approx.f16x2 %0, %1;" : "=r"(r) : "r"(x));
    return r;
}

__device__ __forceinline__ void mma16(float* c, const unsigned* a, unsigned b0, unsigned b1) {
    asm volatile(
        "mma.sync.aligned.m16n8k16.row.col.f32.f16.f16.f32 "
        "{%0,%1,%2,%3},{%4,%5,%6,%7},{%8,%9},{%0,%1,%2,%3};"
        : "+f"(c[0]), "+f"(c[1]), "+f"(c[2]), "+f"(c[3])
        : "r"(a[0]), "r"(a[1]), "r"(a[2]), "r"(a[3]), "r"(b0), "r"(b1));
}

__device__ __forceinline__ void ldsm4(unsigned* r, unsigned addr) {
    asm volatile("ldmatrix.sync.aligned.m8n8.x4.shared.b16 {%0,%1,%2,%3},[%4];"
                 : "=r"(r[0]), "=r"(r[1]), "=r"(r[2]), "=r"(r[3]) : "r"(addr));
}
__device__ __forceinline__ void ldsm4t(unsigned* r, unsigned addr) {
    asm volatile("ldmatrix.sync.aligned.m8n8.x4.trans.shared.b16 {%0,%1,%2,%3},[%4];"
                 : "=r"(r[0]), "=r"(r[1]), "=r"(r[2]), "=r"(r[3]) : "r"(addr));
}
__device__ __forceinline__ void ldsm2t(unsigned* r, unsigned addr) {
    asm volatile("ldmatrix.sync.aligned.m8n8.x2.trans.shared.b16 {%0,%1},[%2];"
                 : "=r"(r[0]), "=r"(r[1]) : "r"(addr));
}

__device__ __forceinline__ void cpa16(unsigned dst, const void* src) {
    asm volatile("cp.async.cg.shared.global [%0],[%1],16;" :: "r"(dst), "l"(src));
}
__device__ __forceinline__ void cpcommit() { asm volatile("cp.async.commit_group;"); }
__device__ __forceinline__ void cpwait0()  { asm volatile("cp.async.wait_group 0;"); }
__device__ __forceinline__ void cpwait1()  { asm volatile("cp.async.wait_group 1;"); }

__device__ __forceinline__ unsigned sptr(const void* p) {
    return (unsigned)__cvta_generic_to_shared(p);
}

// ---------------------------------------------------------------------------
// merged fp32->fp16 conversions + rope table (one launch)
// ---------------------------------------------------------------------------
__device__ __forceinline__ void conv8(const float* s, __half* d) {
    float4 v0 = *(const float4*)s;
    float4 v1 = *(const float4*)(s + 4);
    uint4 o = make_uint4(ph2(v0.x, v0.y), ph2(v0.z, v0.w),
                         ph2(v1.x, v1.y), ph2(v1.z, v1.w));
    *(uint4*)d = o;
}

#define C0 (MROWS * CC / 8)
#define C1 (C0 + CC * HH * DD / 8)
#define C2 (C1 + CC * RR / 8)
#define C3 (C2 + RR * KVW / 8)
#define C4 (C3 + HH * DD * CC / 8)
#define C5 (C4 + TT * 32)                 // rope table entries (1/thread)

__global__ __launch_bounds__(256) void f2h_all(
    const float* __restrict__ x,  const float* __restrict__ wq,
    const float* __restrict__ wdn,const float* __restrict__ wup,
    const float* __restrict__ wo,
    __half* __restrict__ xh, __half* __restrict__ hq, __half* __restrict__ hdn,
    __half* __restrict__ hup, __half* __restrict__ ho, float2* __restrict__ tab)
{
    int i = blockIdx.x * 256 + threadIdx.x;
    if      (i < C0) { int k = i * 8;            conv8(x + k,   xh + k); }
    else if (i < C1) { int k = (i - C0) * 8;     conv8(wq + k,  hq + k); }
    else if (i < C2) { int k = (i - C1) * 8;     conv8(wdn + k, hdn + k); }
    else if (i < C3) { int k = (i - C2) * 8;     conv8(wup + k, hup + k); }
    else if (i < C4) { int k = (i - C3) * 8;     conv8(wo + k,  ho + k); }
    else if (i < C5) {
        int k = i - C4;
        int d = k & 31, t = k >> 5;
        float inv = exp2f(-(float)d * (13.287712379549449f / 32.f));
        float sn, cs;
        sincosf((float)t * inv, &sn, &cs);
        tab[k] = make_float2(cs, sn);
    }
}

// ---------------------------------------------------------------------------
// GEMM core (device function, dynamic smem).
//   EPI 1: fp32 out + bias; EPI 2: fp16 out + RoPE; EPI 3: fp16 out + LN(64)
// ---------------------------------------------------------------------------
template<int BN, int EPI, typename OutT>
__device__ __forceinline__ void gemm_core(char* smem,
    const __half* __restrict__ A, const __half* __restrict__ B,
    OutT* __restrict__ C, int M, int N, int K, int bx, int by,
    const float* __restrict__ bias,
    const float2* __restrict__ rt, float ropeScale, int ropeLimit,
    const float* __restrict__ lng, const float* __restrict__ lnb)
{
    constexpr int NT = BN / 16;
    constexpr int ASTR = 112;
    constexpr int BSTR = (BN == 128) ? 272 : 144;
    constexpr int ASTAGE = 128 * ASTR;
    constexpr int BSTAGE = 32 * BSTR;

    const unsigned uA = sptr(smem);
    const unsigned uB = uA + 2 * ASTAGE;

    const int tid  = threadIdx.x;
    const int lane = tid & 31;
    const int w    = tid >> 5;
    const int g    = lane >> 2;
    const int tig  = lane & 3;
    const int wm   = (w & 3) * 32;
    const int wn   = (w >> 2) * (BN / 2);
    const int m0   = by * 128;
    const int n0   = bx * BN;

    const int far = tid >> 1;
    const int fac = (tid & 1) * 2;
    const int fbk = tid >> 3;
    const int fbc = (BN == 128) ? (tid & 7) * 2 : (tid & 7);

    const __half* Asrc = A + (size_t)(m0 + far) * K + fac * 8;
    const __half* Bsrc = B + (size_t)fbk * N + n0 + fbc * 8;
    const unsigned adst = uA + far * ASTR + fac * 16;
    const unsigned bdst = uB + fbk * BSTR + fbc * 16;

    float acc[2][NT][4];
#pragma unroll
    for (int mt = 0; mt < 2; ++mt)
#pragma unroll
        for (int nt = 0; nt < NT; ++nt)
#pragma unroll
            for (int i = 0; i < 4; ++i) acc[mt][nt][i] = 0.f;

    const int niters = K >> 5;

    cpa16(adst, Asrc); cpa16(adst + 16, Asrc + 8);
    cpa16(bdst, Bsrc);
    if (BN == 128) cpa16(bdst + 16, Bsrc + 8);
    cpcommit();

    for (int it = 0; it < niters; ++it) {
        if (it + 1 < niters) {
            const int st = (it + 1) & 1;
            const __half* as = Asrc + (it + 1) * 32;
            const __half* bs = Bsrc + (size_t)(it + 1) * 32 * N;
            cpa16(adst + st * ASTAGE, as); cpa16(adst + st * ASTAGE + 16, as + 8);
            cpa16(bdst + st * BSTAGE, bs);
            if (BN == 128) cpa16(bdst + st * BSTAGE + 16, bs + 8);
            cpcommit();
            cpwait1();
        } else {
            cpwait0();
        }
        __syncthreads();

        const int st = it & 1;
        const unsigned aAb = uA + st * ASTAGE + (wm + (lane & 15)) * ASTR + ((lane >> 4) << 4);
        unsigned af[2][2][4];
#pragma unroll
        for (int kc = 0; kc < 2; ++kc)
#pragma unroll
            for (int mt = 0; mt < 2; ++mt)
                ldsm4(af[kc][mt], aAb + mt * 16 * ASTR + kc * 32);

        const unsigned aBb = uB + st * BSTAGE + (lane & 15) * BSTR
                           + (wn + ((lane >> 4) << 3)) * 2;
#pragma unroll
        for (int kc = 0; kc < 2; ++kc) {
#pragma unroll
            for (int np = 0; np < NT / 2; ++np) {
                unsigned bf[4];
                ldsm4t(bf, aBb + kc * 16 * BSTR + np * 32);
                mma16(acc[0][2 * np],     af[kc][0], bf[0], bf[1]);
                mma16(acc[1][2 * np],     af[kc][1], bf[0], bf[1]);
                mma16(acc[0][2 * np + 1], af[kc][0], bf[2], bf[3]);
                mma16(acc[1][2 * np + 1], af[kc][1], bf[2], bf[3]);
            }
        }
        __syncthreads();
    }

    // ------------------------- epilogues -------------------------
    if constexpr (EPI == 1) {
#pragma unroll
        for (int mt = 0; mt < 2; ++mt) {
            const int r0 = m0 + wm + mt * 16 + g;
#pragma unroll
            for (int nt = 0; nt < NT; ++nt) {
                const int c0 = n0 + wn + nt * 8 + 2 * tig;
                const float b0 = bias[c0], b1 = bias[c0 + 1];
                *(float2*)((float*)C + (size_t)r0 * N + c0) =
                    make_float2(acc[mt][nt][0] + b0, acc[mt][nt][1] + b1);
                *(float2*)((float*)C + (size_t)(r0 + 8) * N + c0) =
                    make_float2(acc[mt][nt][2] + b0, acc[mt][nt][3] + b1);
            }
        }
    } else if constexpr (EPI == 2) {
        const bool doRope = (n0 + wn) < ropeLimit;
        __half* Ch = (__half*)C;
#pragma unroll
        for (int mt = 0; mt < 2; ++mt) {
            const int r0 = m0 + wm + mt * 16 + g;
            const int t0 = r0 & (TT - 1);
#pragma unroll
            for (int ntp = 0; ntp < 4; ++ntp) {
                const int clo = n0 + wn + ntp * 8 + 2 * tig;
                float lo0[2], hi0[2], lo1[2], hi1[2];
                if (doRope) {
#pragma unroll
                    for (int j = 0; j < 2; ++j) {
                        const int d = ntp * 8 + 2 * tig + j;
                        const float2 cs0 = rt[t0 * 32 + d];
                        const float2 cs1 = rt[(t0 + 8) * 32 + d];
                        const float xl0 = acc[mt][ntp][j],     xh0 = acc[mt][ntp + 4][j];
                        const float xl1 = acc[mt][ntp][j + 2], xh1 = acc[mt][ntp + 4][j + 2];
                        lo0[j] = xl0 * cs0.x - xh0 * cs0.y;
                        hi0[j] = xh0 * cs0.x + xl0 * cs0.y;
                        lo1[j] = xl1 * cs1.x - xh1 * cs1.y;
                        hi1[j] = xh1 * cs1.x + xl1 * cs1.y;
                    }
                } else {
#pragma unroll
                    for (int j = 0; j < 2; ++j) {
                        lo0[j] = acc[mt][ntp][j];     hi0[j] = acc[mt][ntp + 4][j];
                        lo1[j] = acc[mt][ntp][j + 2]; hi1[j] = acc[mt][ntp + 4][j + 2];
                    }
                }
                const float s = ropeScale;
                *(unsigned*)(Ch + (size_t)r0 * N + clo)        = ph2(lo0[0] * s, lo0[1] * s);
                *(unsigned*)(Ch + (size_t)r0 * N + clo + 32)   = ph2(hi0[0] * s, hi0[1] * s);
                *(unsigned*)(Ch + (size_t)(r0 + 8) * N + clo)      = ph2(lo1[0] * s, lo1[1] * s);
                *(unsigned*)(Ch + (size_t)(r0 + 8) * N + clo + 32) = ph2(hi1[0] * s, hi1[1] * s);
            }
        }
    } else if constexpr (EPI == 3) {
        float2* red = (float2*)smem;
        float rs[2][2], rq[2][2];
#pragma unroll
        for (int mt = 0; mt < 2; ++mt)
#pragma unroll
            for (int hh = 0; hh < 2; ++hh) {
                float s = 0.f, sq = 0.f;
#pragma unroll
                for (int nt = 0; nt < NT; ++nt)
#pragma unroll
                    for (int j = 0; j < 2; ++j) {
                        float v = acc[mt][nt][2 * hh + j];
                        s += v; sq += v * v;
                    }
                s  += __shfl_xor_sync(0xffffffffu, s, 1);
                s  += __shfl_xor_sync(0xffffffffu, s, 2);
                sq += __shfl_xor_sync(0xffffffffu, sq, 1);
                sq += __shfl_xor_sync(0xffffffffu, sq, 2);
                rs[mt][hh] = s; rq[mt][hh] = sq;
            }
        if (tig == 0) {
#pragma unroll
            for (int mt = 0; mt < 2; ++mt)
#pragma unroll
                for (int hh = 0; hh < 2; ++hh) {
                    const int rl = wm + mt * 16 + g + hh * 8;
                    red[(w >> 2) * 128 + rl] = make_float2(rs[mt][hh], rq[mt][hh]);
                }
        }
        __syncthreads();
        __half* Ch = (__half*)C;
#pragma unroll
        for (int mt = 0; mt < 2; ++mt)
#pragma unroll
            for (int hh = 0; hh < 2; ++hh) {
                const int rl = wm + mt * 16 + g + hh * 8;
                const float2 a = red[rl], bb = red[128 + rl];
                const float mean = (a.x + bb.x) * (1.f / 64.f);
                const float var  = (a.y + bb.y) * (1.f / 64.f) - mean * mean;
                const float inv  = rsqrtf(var + 1e-5f);
                const int r0 = m0 + rl;
#pragma unroll
                for (int nt = 0; nt < NT; ++nt) {
                    const int c = wn + nt * 8 + 2 * tig;
                    const float v0 = (acc[mt][nt][2 * hh]     - mean) * inv * lng[c]     + lnb[c];
                    const float v1 = (acc[mt][nt][2 * hh + 1] - mean) * inv * lng[c + 1] + lnb[c + 1];
                    *(unsigned*)(Ch + (size_t)r0 * N + c) = ph2(v0, v1);
                }
            }
    }
}

// standalone GEMM wrapper
template<int BN, int EPI, typename OutT>
__global__ __launch_bounds__(256) void hgemm16(
    const __half* __restrict__ A, const __half* __restrict__ B,
    OutT* __restrict__ C, int M, int N, int K,
    const float* __restrict__ bias,
    const float2* __restrict__ rt, float ropeScale, int ropeLimit,
    const float* __restrict__ lng, const float* __restrict__ lnb)
{
    extern __shared__ __align__(16) char sm[];
    gemm_core<BN, EPI, OutT>(sm, A, B, C, M, N, K, blockIdx.x, blockIdx.y,
                             bias, rt, ropeScale, ropeLimit, lng, lnb);
}

// fused Wq (RoPE) + Wdown (LayerNorm): gridDim.x = 7
__global__ __launch_bounds__(256) void qdown_k(
    const __half* __restrict__ xh, const __half* __restrict__ wq,
    const __half* __restrict__ wdn, __half* __restrict__ q16,
    __half* __restrict__ ckvh, const float2* __restrict__ rt, float qscale,
    const float* __restrict__ lng, const float* __restrict__ lnb)
{
    extern __shared__ __align__(16) char sm[];
    if (blockIdx.x < 6)
        gemm_core<128, 2, __half>(sm, xh, wq, q16, MROWS, CC, CC,
                                  blockIdx.x, blockIdx.y,
                                  nullptr, rt, qscale, CC, nullptr, nullptr);
    else
        gemm_core<64, 3, __half>(sm, xh, wdn, ckvh, MROWS, RR, CC,
                                 0, blockIdx.y,
                                 nullptr, nullptr, 0.f, 0, lng, lnb);
}

#define GEMM_SMEM (2 * 128 * 112 + 2 * 32 * 272)   // 46080

// ---------------------------------------------------------------------------
// Causal flash attention: fp16 in (q pre-scaled by SCALE*log2e), fp16 out.
// l computed by MMA against the all-ones V pad column; exp in fp16x2.
// ---------------------------------------------------------------------------
#define KVBYTES (64 * 144)
#define QBYTES  (128 * 144)
#define ASMEM   (QBYTES + 4 * KVBYTES)   // 55296

__global__ __launch_bounds__(256, 2) void attn_f16(
    const __half* __restrict__ q, const __half* __restrict__ kv, __half* __restrict__ ao)
{
    extern __shared__ __align__(16) char sm[];
    const unsigned uQ = sptr(sm);
    const unsigned uK = uQ + QBYTES;
    const unsigned uV = uK + 2 * KVBYTES;

    const int tid  = threadIdx.x;
    const int lane = tid & 31;
    const int w    = tid >> 5;
    const int g    = lane >> 2;
    const int tig  = lane & 3;
    const int qi   = (gridDim.x - 1) - blockIdx.x;
    const int i0   = qi * 128;
    const int h    = blockIdx.y;
    const int b    = blockIdx.z;
    const int rb   = w * 16;
    const int row_min = i0 + rb;
    const int row_max = row_min + 15;

    // Q fill
    {
        const int r  = tid >> 1;
        const int hh = (tid & 1) * 32;
        const uint4* src = (const uint4*)(q + (size_t)(b * TT + i0 + r) * CC + h * DD + hh);
        char* dst = sm + r * 144 + hh * 2;
        uint4 v0 = src[0], v1 = src[1], v2 = src[2], v3 = src[3];
        *(uint4*)dst = v0; *(uint4*)(dst + 16) = v1;
        *(uint4*)(dst + 32) = v2; *(uint4*)(dst + 48) = v3;
    }
    // V pad columns = 1.0h (both stages; cp.async never touches bytes 128..143)
    if (tid < 128) {
        const int stg = tid >> 6;
        const int r   = tid & 63;
        *(uint4*)(sm + QBYTES + (2 + stg) * KVBYTES + r * 144 + 128) =
            make_uint4(0x3C003C00u, 0x3C003C00u, 0x3C003C00u, 0x3C003C00u);
    }
    __syncwarp();

    unsigned qa[4][4];
    {
        const unsigned aQ = uQ + (rb + (lane & 15)) * 144 + ((lane >> 4) << 4);
#pragma unroll
        for (int kc = 0; kc < 4; ++kc) ldsm4(qa[kc], aQ + kc * 32);
    }

    const int fr = tid >> 2;
    const int fc = (tid & 3) * 2;
    const size_t kvrow0 = (size_t)(b * TT) * KVW + h * DD + fc * 8;

    {
        const __half* ks = kv + kvrow0 + (size_t)fr * KVW;
        const unsigned kd = uK + fr * 144 + fc * 16;
        cpa16(kd, ks); cpa16(kd + 16, ks + 8);
        const unsigned vd = uV + fr * 144 + fc * 16;
        cpa16(vd, ks + HH * DD); cpa16(vd + 16, ks + HH * DD + 8);
    }
    cpcommit();

    float mr0 = -INFINITY, mr1 = -INFINITY;
    float oacc[8][4], osum[4];
#pragma unroll
    for (int nt = 0; nt < 8; ++nt)
#pragma unroll
        for (int i = 0; i < 4; ++i) oacc[nt][i] = 0.f;
#pragma unroll
    for (int i = 0; i < 4; ++i) osum[i] = 0.f;

    const int ntile = 2 * qi + 2;
    for (int jt = 0; jt < ntile; ++jt) {
        if (jt + 1 < ntile) {
            const int st = (jt + 1) & 1;
            const __half* ks = kv + kvrow0 + (size_t)((jt + 1) * 64 + fr) * KVW;
            const unsigned kd = uK + st * KVBYTES + fr * 144 + fc * 16;
            cpa16(kd, ks); cpa16(kd + 16, ks + 8);
            const unsigned vd = uV + st * KVBYTES + fr * 144 + fc * 16;
            cpa16(vd, ks + HH * DD); cpa16(vd + 16, ks + HH * DD + 8);
            cpcommit();
            cpwait1();
        } else {
            cpwait0();
        }
        __syncthreads();

        const int j0 = jt * 64;
        if (j0 <= row_max) {
            const int st = jt & 1;

            // --- S = Q K^T ---
            float sacc[8][4];
#pragma unroll
            for (int nt = 0; nt < 8; ++nt)
#pragma unroll
                for (int i = 0; i < 4; ++i) sacc[nt][i] = 0.f;

            const unsigned aK = uK + st * KVBYTES
                              + ((lane & 7) + ((lane & 16) >> 1)) * 144 + ((lane & 8) << 1);
#pragma unroll
            for (int kc = 0; kc < 4; ++kc) {
#pragma unroll
                for (int np = 0; np < 4; ++np) {
                    unsigned bf[4];
                    ldsm4(bf, aK + np * 16 * 144 + kc * 32);
                    mma16(sacc[2 * np],     qa[kc], bf[0], bf[1]);
                    mma16(sacc[2 * np + 1], qa[kc], bf[2], bf[3]);
                }
            }

            // --- causal mask (partial tile only) ---
            if (j0 + 63 > row_min) {
                const int r0g = row_min + g, r1g = r0g + 8;
#pragma unroll
                for (int nt = 0; nt < 8; ++nt) {
                    const int c = j0 + nt * 8 + 2 * tig;
                    if (c > r0g)     sacc[nt][0] = -INFINITY;
                    if (c + 1 > r0g) sacc[nt][1] = -INFINITY;
                    if (c > r1g)     sacc[nt][2] = -INFINITY;
                    if (c + 1 > r1g) sacc[nt][3] = -INFINITY;
                }
            }

            // --- online softmax (base 2): max, rescale, fp16 exp ---
            float tm0 = -INFINITY, tm1 = -INFINITY;
#pragma unroll
            for (int nt = 0; nt < 8; ++nt) {
                tm0 = fmaxf(tm0, fmaxf(sacc[nt][0], sacc[nt][1]));
                tm1 = fmaxf(tm1, fmaxf(sacc[nt][2], sacc[nt][3]));
            }
            tm0 = fmaxf(tm0, __shfl_xor_sync(0xffffffffu, tm0, 1));
            tm0 = fmaxf(tm0, __shfl_xor_sync(0xffffffffu, tm0, 2));
            tm1 = fmaxf(tm1, __shfl_xor_sync(0xffffffffu, tm1, 1));
            tm1 = fmaxf(tm1, __shfl_xor_sync(0xffffffffu, tm1, 2));

            const float mn0 = fmaxf(mr0, tm0), mn1 = fmaxf(mr1, tm1);
            const float al0 = exp2f(mr0 - mn0), al1 = exp2f(mr1 - mn1);
            mr0 = mn0; mr1 = mn1;

            unsigned pfr[4][4];
#pragma unroll
            for (int kk = 0; kk < 4; ++kk) {
                pfr[kk][0] = ex2h2(ph2(sacc[2 * kk][0] - mn0,     sacc[2 * kk][1] - mn0));
                pfr[kk][1] = ex2h2(ph2(sacc[2 * kk][2] - mn1,     sacc[2 * kk][3] - mn1));
                pfr[kk][2] = ex2h2(ph2(sacc[2 * kk + 1][0] - mn0, sacc[2 * kk + 1][1] - mn0));
                pfr[kk][3] = ex2h2(ph2(sacc[2 * kk + 1][2] - mn1, sacc[2 * kk + 1][3] - mn1));
            }

#pragma unroll
            for (int nt = 0; nt < 8; ++nt) {
                oacc[nt][0] *= al0; oacc[nt][1] *= al0;
                oacc[nt][2] *= al1; oacc[nt][3] *= al1;
            }
            osum[0] *= al0; osum[1] *= al0;
            osum[2] *= al1; osum[3] *= al1;

            // --- O += P V ; l += P 1 (pad column) ---
            const unsigned aV  = uV + st * KVBYTES + (lane & 15) * 144 + (lane & 16);
            const unsigned aVs = uV + st * KVBYTES + (lane & 15) * 144 + 128;
#pragma unroll
            for (int kc = 0; kc < 4; ++kc) {
#pragma unroll
                for (int np = 0; np < 4; ++np) {
                    unsigned bf[4];
                    ldsm4t(bf, aV + kc * 16 * 144 + np * 32);
                    mma16(oacc[2 * np],     pfr[kc], bf[0], bf[1]);
                    mma16(oacc[2 * np + 1], pfr[kc], bf[2], bf[3]);
                }
                unsigned bl[2];
                ldsm2t(bl, aVs + kc * 16 * 144);
                mma16(osum, pfr[kc], bl[0], bl[1]);
            }
        }
        __syncthreads();
    }

    const float inv0 = 1.f / osum[0], inv1 = 1.f / osum[2];
    __half* dst0 = ao + (size_t)(b * TT + i0 + rb + g) * CC + h * DD;
    __half* dst1 = dst0 + (size_t)8 * CC;
#pragma unroll
    for (int nt = 0; nt < 8; ++nt) {
        const int c = nt * 8 + 2 * tig;
        *(unsigned*)(dst0 + c) = ph2(oacc[nt][0] * inv0, oacc[nt][1] * inv0);
        *(unsigned*)(dst1 + c) = ph2(oacc[nt][2] * inv1, oacc[nt][3] * inv1);
    }
}

// ---------------------------------------------------------------------------
// Launch
// ---------------------------------------------------------------------------
extern "C" void kernel_launch(void* const* d_in, const int* in_sizes, int n_in,
                              void* d_out, int out_size)
{
    const float* x     = (const float*)d_in[0];
    const float* Wq    = (const float*)d_in[1];
    const float* Wdown = (const float*)d_in[2];
    const float* ln_g  = (const float*)d_in[3];
    const float* ln_b  = (const float*)d_in[4];
    const float* Wup   = (const float*)d_in[5];
    const float* Wo    = (const float*)d_in[6];
    const float* bo    = (const float*)d_in[7];
    float* out = (float*)d_out;

    void *pxh, *pq, *pckvh, *pkv, *pao, *pwq, *pwdn, *pwup, *pwo, *prt;
    cudaGetSymbolAddress(&pxh,  g_xh);
    cudaGetSymbolAddress(&pq,   g_q16);
    cudaGetSymbolAddress(&pckvh,g_ckvh);
    cudaGetSymbolAddress(&pkv,  g_kv16);
    cudaGetSymbolAddress(&pao,  g_ao16);
    cudaGetSymbolAddress(&pwq,  g_wq);
    cudaGetSymbolAddress(&pwdn, g_wdn);
    cudaGetSymbolAddress(&pwup, g_wup);
    cudaGetSymbolAddress(&pwo,  g_wo);
    cudaGetSymbolAddress(&prt,  g_rt);
    __half* xh   = (__half*)pxh;
    __half* q16  = (__half*)pq;
    __half* ckvh = (__half*)pckvh;
    __half* kv16 = (__half*)pkv;
    __half* ao16 = (__half*)pao;
    __half* wq   = (__half*)pwq;
    __half* wdn  = (__half*)pwdn;
    __half* wup  = (__half*)pwup;
    __half* wo   = (__half*)pwo;
    float2* rt   = (float2*)prt;

    cudaFuncSetAttribute(attn_f16, cudaFuncAttributeMaxDynamicSharedMemorySize, ASMEM);

    // 0) conversions + rope table (one launch)
    f2h_all<<<C5 / 256, 256>>>(x, Wq, Wdown, Wup, Wo, xh, wq, wdn, wup, wo, rt);

    // 1) fused: q = rope(x@Wq)*SCALE*log2e  AND  ckv = layernorm(x@Wdown)
    qdown_k<<<dim3(7, MROWS / 128), 256, GEMM_SMEM>>>(
        xh, wq, wdn, q16, ckvh, rt, SCALE * LOG2E, ln_g, ln_b);

    // 2) kv = ckv @ Wup, rope on K half
    hgemm16<128, 2, __half><<<dim3(KVW / 128, MROWS / 128), 256, GEMM_SMEM>>>(
        ckvh, wup, kv16, MROWS, KVW, RR, nullptr, rt, 1.0f, HH * DD, nullptr, nullptr);

    // 3) attention
    attn_f16<<<dim3(TT / 128, HH, BB), 256, ASMEM>>>(q16, kv16, ao16);

    // 4) out = ao @ Wo + bo
    hgemm16<128, 1, float><<<dim3(CC / 128, MROWS / 128), 256, GEMM_SMEM>>>(
        ao16, wo, out, MROWS, CC, CC, bo, nullptr, 0.f, 0, nullptr, nullptr);
}